// round 8
// baseline (speedup 1.0000x reference)
#include <cuda_runtime.h>

// ---------------------------------------------------------------------------
// Problem constants
// ---------------------------------------------------------------------------
#define QLEN  1024
#define BSZ   4
#define NH    16
#define DH    64
#define DM    1024
#define NTOK  4096          // QLEN*BSZ
#define NBH   64            // NH*BSZ  (batch index z = h*4 + b)
#define ATT_SCALE 0.125f    // 1/sqrt(64)

// ---------------------------------------------------------------------------
// Device scratch (static __device__ arrays -- the sanctioned workaround)
// ---------------------------------------------------------------------------
__device__ float g_heads [(long)NTOK * 3072];              //  50 MB  [tok][3072]
__device__ float g_convin[(long)3 * NBH * DH * QLEN];      //  50 MB  [s][hb][d][l]
__device__ float g_rproj [(long)QLEN * DM];                //   4 MB  [m][c]
__device__ float g_rhk   [(long)DM * QLEN];                //   4 MB  [c][m]
__device__ float g_qw    [(long)NBH * DH * QLEN];          //  17 MB  [hb][d][l]  q_h + r_w_bias
__device__ float g_qr    [(long)NBH * DH * QLEN];          //  17 MB  q_h + r_r_bias
__device__ float g_kh    [(long)NBH * DH * QLEN];          //  17 MB
__device__ float g_vh    [(long)NBH * DH * QLEN];          //  17 MB
__device__ float g_ac    [(long)NBH * QLEN * QLEN];        // 256 MB  [z][i][j]  (becomes prob)
__device__ float g_bd    [(long)NBH * QLEN * QLEN];        // 256 MB  [z][i][m]
__device__ float g_vec   [(long)NTOK * DM];                //  17 MB  [tok][h*64+d]
__device__ float g_attn  [(long)NTOK * DM];                //  17 MB
__device__ float g_wpad  [3 * DH * DH * 8];                // padded conv weights

// ---------------------------------------------------------------------------
// Generic batched SGEMM: C[m][n] = sum_k A(k,m)*B(k,n)
//   AT=true : A stored [K][M] (M contiguous, lda = K-row stride)  -- "TN" side
//   AT=false: A stored [M][K] (K contiguous)                      -- "NT" side
//   same for BT.  CMODE 0: C = Cb + z*cStride ; CMODE 1: PV scatter layout.
// ---------------------------------------------------------------------------
template<int BM,int BN,int BK,int TM,int TN,bool AT,bool BT,int CMODE>
__global__ __launch_bounds__((BM/TM)*(BN/TN))
void gemm_k(const float* __restrict__ Ab, const float* __restrict__ Bb,
            float* __restrict__ Cb,
            int K, int lda, int ldb, int ldc,
            long aStride, long bStride, int bShift, long cStride)
{
    constexpr int TX = BN / TN;
    constexpr int TY = BM / TM;
    constexpr int NT = TX * TY;
    const int tid = threadIdx.x;
    const int z   = blockIdx.z;

    const float* A = Ab + (long)z * aStride;
    const float* B = Bb + (long)(bShift ? (z >> 2) : z) * bStride;
    float* C;
    if (CMODE == 0) C = Cb + (long)z * cStride;
    else            C = Cb + (long)(z & 3) * 1024 + (long)(z >> 2) * 64;  // vec scatter

    const int m0 = blockIdx.y * BM;
    const int n0 = blockIdx.x * BN;

    __shared__ float As[BK][BM + 4];
    __shared__ float Bs[BK][BN + 4];

    const int tx = tid % TX;
    const int ty = tid / TX;

    float acc[TM][TN];
#pragma unroll
    for (int i = 0; i < TM; i++)
#pragma unroll
        for (int j = 0; j < TN; j++) acc[i][j] = 0.f;

    for (int k0 = 0; k0 < K; k0 += BK) {
        if (AT) {
            constexpr int NF4 = BM * BK / 4;
            for (int i = tid; i < NF4; i += NT) {
                int r = i / (BM / 4);
                int c = i % (BM / 4);
                float4 v = *(const float4*)(A + (long)(k0 + r) * lda + m0 + c * 4);
                *(float4*)&As[r][c * 4] = v;
            }
        } else {
            constexpr int NF4 = BM * BK / 4;
            for (int i = tid; i < NF4; i += NT) {
                int r = i / (BK / 4);
                int q = i % (BK / 4);
                float4 v = *(const float4*)(A + (long)(m0 + r) * lda + k0 + q * 4);
                As[q * 4 + 0][r] = v.x;
                As[q * 4 + 1][r] = v.y;
                As[q * 4 + 2][r] = v.z;
                As[q * 4 + 3][r] = v.w;
            }
        }
        if (BT) {
            constexpr int NF4 = BN * BK / 4;
            for (int i = tid; i < NF4; i += NT) {
                int r = i / (BN / 4);
                int c = i % (BN / 4);
                float4 v = *(const float4*)(B + (long)(k0 + r) * ldb + n0 + c * 4);
                *(float4*)&Bs[r][c * 4] = v;
            }
        } else {
            constexpr int NF4 = BN * BK / 4;
            for (int i = tid; i < NF4; i += NT) {
                int r = i / (BK / 4);
                int q = i % (BK / 4);
                float4 v = *(const float4*)(B + (long)(n0 + r) * ldb + k0 + q * 4);
                Bs[q * 4 + 0][r] = v.x;
                Bs[q * 4 + 1][r] = v.y;
                Bs[q * 4 + 2][r] = v.z;
                Bs[q * 4 + 3][r] = v.w;
            }
        }
        __syncthreads();
#pragma unroll
        for (int kk = 0; kk < BK; kk++) {
            float a[TM], b[TN];
#pragma unroll
            for (int u = 0; u < TM / 4; u++)
                *(float4*)&a[u * 4] = *(const float4*)&As[kk][ty * TM + u * 4];
#pragma unroll
            for (int u = 0; u < TN / 4; u++)
                *(float4*)&b[u * 4] = *(const float4*)&Bs[kk][tx * TN + u * 4];
#pragma unroll
            for (int i = 0; i < TM; i++)
#pragma unroll
                for (int j = 0; j < TN; j++)
                    acc[i][j] += a[i] * b[j];
        }
        __syncthreads();
    }

#pragma unroll
    for (int i = 0; i < TM; i++) {
        long row = m0 + ty * TM + i;
#pragma unroll
        for (int u = 0; u < TN / 4; u++) {
            float4 v = make_float4(acc[i][u*4+0], acc[i][u*4+1],
                                   acc[i][u*4+2], acc[i][u*4+3]);
            *(float4*)(C + row * ldc + n0 + tx * TN + u * 4) = v;
        }
    }
}

// ---------------------------------------------------------------------------
// Transpose heads[tok=(q*4+b)][c=0..3071] -> convin[s][h*4+b][d][q]
// ---------------------------------------------------------------------------
__global__ void transpose_heads_k(const float* __restrict__ heads,
                                  float* __restrict__ convin)
{
    __shared__ float tile[32][33];
    const int q0 = blockIdx.x * 32;
    const int c0 = blockIdx.y * 32;
    const int b  = blockIdx.z;
    const int x = threadIdx.x, y = threadIdx.y;
#pragma unroll
    for (int yy = 0; yy < 32; yy += 8)
        tile[yy + y][x] = heads[((long)(q0 + yy + y) * 4 + b) * 3072 + c0 + x];
    __syncthreads();
#pragma unroll
    for (int yy = 0; yy < 32; yy += 8) {
        int ch = c0 + yy + y;
        int s = ch >> 10, rem = ch & 1023, h = rem >> 6, d = rem & 63;
        convin[((long)(s * 64 + h * 4 + b) * 64 + d) * 1024 + q0 + x] = tile[x][yy + y];
    }
}

// Transpose rproj[m][c] -> rhk[c][m]
__global__ void transpose_r_k(const float* __restrict__ rproj, float* __restrict__ rhk)
{
    __shared__ float tile[32][33];
    const int m0 = blockIdx.x * 32;
    const int c0 = blockIdx.y * 32;
    const int x = threadIdx.x, y = threadIdx.y;
#pragma unroll
    for (int yy = 0; yy < 32; yy += 8)
        tile[yy + y][x] = rproj[(long)(m0 + yy + y) * 1024 + c0 + x];
    __syncthreads();
#pragma unroll
    for (int yy = 0; yy < 32; yy += 8)
        rhk[(long)(c0 + yy + y) * 1024 + m0 + x] = tile[x][yy + y];
}

// Pad conv weights [O][I][7] -> [s][O][I][8] (8th tap = 0) for float4 loads
__global__ void prep_w_k(const float* __restrict__ wq, const float* __restrict__ wk,
                         const float* __restrict__ wv, float* __restrict__ wpad)
{
    int i = blockIdx.x * 256 + threadIdx.x;
    if (i >= 3 * 64 * 64 * 8) return;
    int t  = i & 7;
    int oi = (i >> 3) & 4095;
    int s  = i >> 15;
    const float* src = (s == 0) ? wq : (s == 1) ? wk : wv;
    wpad[i] = (t < 7) ? src[oi * 7 + t] : 0.f;
}

// ---------------------------------------------------------------------------
// Conv1d (same padding, K=7, full 64x64 channel mix), fused bias epilogues.
// Block: (l-tile of 128, hb, section). 256 threads: g=tid/32 owns 8 douts,
// lsub=tid%32 owns 4 l positions. Weights via uniform LDG (L1/L2-resident).
// ---------------------------------------------------------------------------
__global__ __launch_bounds__(256)
void conv_k(const float* __restrict__ convin, const float* __restrict__ wpad,
            const float* __restrict__ cbq, const float* __restrict__ cbk,
            const float* __restrict__ cbv,
            const float* __restrict__ rwb, const float* __restrict__ rrb,
            float* __restrict__ qw, float* __restrict__ qr,
            float* __restrict__ kh, float* __restrict__ vh)
{
    const int s  = blockIdx.z;
    const int hb = blockIdx.y;
    const int l0 = blockIdx.x * 128;
    const float* x  = convin + (long)(s * 64 + hb) * (64 * 1024);
    const float* wp = wpad + (long)s * (64 * 64 * 8);

    __shared__ float xs[64][136];
    for (int i = threadIdx.x; i < 64 * 134; i += 256) {
        int din = i / 134, c = i % 134;
        int gl = l0 - 3 + c;
        xs[din][c] = (gl >= 0 && gl < 1024) ? x[(long)din * 1024 + gl] : 0.f;
    }
    __syncthreads();

    const int lsub = threadIdx.x & 31;
    const int g    = threadIdx.x >> 5;

    float acc[8][4];
#pragma unroll
    for (int o = 0; o < 8; o++)
#pragma unroll
        for (int j = 0; j < 4; j++) acc[o][j] = 0.f;

    for (int din = 0; din < 64; din++) {
        float xv[4][7];
#pragma unroll
        for (int j = 0; j < 4; j++)
#pragma unroll
            for (int t = 0; t < 7; t++)
                xv[j][t] = xs[din][lsub + 32 * j + t];
#pragma unroll
        for (int o = 0; o < 8; o++) {
            const float4* wr = (const float4*)(wp + ((g * 8 + o) * 64 + din) * 8);
            float4 wa = __ldg(wr);
            float4 wb = __ldg(wr + 1);
            float wv[7] = {wa.x, wa.y, wa.z, wa.w, wb.x, wb.y, wb.z};
#pragma unroll
            for (int t = 0; t < 7; t++)
#pragma unroll
                for (int j = 0; j < 4; j++)
                    acc[o][j] += wv[t] * xv[j][t];
        }
    }

    const int h = hb >> 2;
#pragma unroll
    for (int o = 0; o < 8; o++) {
        int dout = g * 8 + o;
        long base = ((long)hb * 64 + dout) * 1024 + l0 + lsub;
        if (s == 0) {
            float bv = cbq[dout];
            float aw = rwb[h * 64 + dout];
            float ar = rrb[h * 64 + dout];
#pragma unroll
            for (int j = 0; j < 4; j++) {
                float v = acc[o][j] + bv;
                qw[base + 32 * j] = v + aw;
                qr[base + 32 * j] = v + ar;
            }
        } else if (s == 1) {
            float bv = cbk[dout];
#pragma unroll
            for (int j = 0; j < 4; j++) kh[base + 32 * j] = acc[o][j] + bv;
        } else {
            float bv = cbv[dout];
#pragma unroll
            for (int j = 0; j < 4; j++) vh[base + 32 * j] = acc[o][j] + bv;
        }
    }
}

// ---------------------------------------------------------------------------
// Fused rel-shift + causal mask + softmax, in-place into the AC buffer.
// For row (z,i):  score[j] = (AC[i,j] + BDraw[i, j + 1023 - i]) * SCALE, j<=i.
// Writes prob[j] for all j in [0,1024) (zeros beyond i) -> PV is a dense GEMM.
// ---------------------------------------------------------------------------
__global__ __launch_bounds__(256)
void softmax_k(float* __restrict__ acbuf, const float* __restrict__ bdbuf)
{
    const int i = blockIdx.x;
    const int z = blockIdx.y;
    float* ac       = acbuf + (long)z * (1024L * 1024) + (long)i * 1024;
    const float* bd = bdbuf + (long)z * (1024L * 1024) + (long)i * 1024 + (1023 - i);
    const int n = i + 1;
    __shared__ float red[8];
    const int tid = threadIdx.x;
    const int lane = tid & 31, wid = tid >> 5;

    float mx = -1e30f;
    for (int j = tid; j < n; j += 256)
        mx = fmaxf(mx, (ac[j] + bd[j]) * ATT_SCALE);
#pragma unroll
    for (int o = 16; o > 0; o >>= 1)
        mx = fmaxf(mx, __shfl_xor_sync(0xffffffffu, mx, o));
    if (lane == 0) red[wid] = mx;
    __syncthreads();
    if (tid == 0) {
        float m = red[0];
#pragma unroll
        for (int k = 1; k < 8; k++) m = fmaxf(m, red[k]);
        red[0] = m;
    }
    __syncthreads();
    const float MX = red[0];
    __syncthreads();

    float sum = 0.f;
    for (int j = tid; j < n; j += 256) {
        float e = __expf((ac[j] + bd[j]) * ATT_SCALE - MX);
        ac[j] = e;
        sum += e;
    }
#pragma unroll
    for (int o = 16; o > 0; o >>= 1)
        sum += __shfl_xor_sync(0xffffffffu, sum, o);
    if (lane == 0) red[wid] = sum;
    __syncthreads();
    if (tid == 0) {
        float sm = 0.f;
#pragma unroll
        for (int k = 0; k < 8; k++) sm += red[k];
        red[0] = 1.f / sm;
    }
    __syncthreads();
    const float inv = red[0];
    for (int j = tid; j < 1024; j += 256)
        ac[j] = (j < n) ? ac[j] * inv : 0.f;
}

// ---------------------------------------------------------------------------
// Fused residual + LayerNorm over the last dim (1024)
// ---------------------------------------------------------------------------
__global__ __launch_bounds__(256)
void ln_k(const float* __restrict__ w, const float* __restrict__ attn,
          const float* __restrict__ gamma, const float* __restrict__ beta,
          float* __restrict__ out)
{
    const long t = blockIdx.x;
    __shared__ float xs[1024];
    __shared__ float red[8];
    const int tid = threadIdx.x, lane = tid & 31, wid = tid >> 5;

    float s = 0.f;
    for (int j = tid; j < 1024; j += 256) {
        float v = w[t * 1024 + j] + attn[t * 1024 + j];
        xs[j] = v;
        s += v;
    }
#pragma unroll
    for (int o = 16; o > 0; o >>= 1) s += __shfl_xor_sync(0xffffffffu, s, o);
    if (lane == 0) red[wid] = s;
    __syncthreads();
    if (tid == 0) {
        float tot = 0.f;
#pragma unroll
        for (int k = 0; k < 8; k++) tot += red[k];
        red[0] = tot * (1.f / 1024.f);
    }
    __syncthreads();
    const float mu = red[0];
    __syncthreads();

    float vs = 0.f;
    for (int j = tid; j < 1024; j += 256) {
        float d = xs[j] - mu;
        vs += d * d;
    }
#pragma unroll
    for (int o = 16; o > 0; o >>= 1) vs += __shfl_xor_sync(0xffffffffu, vs, o);
    if (lane == 0) red[wid] = vs;
    __syncthreads();
    if (tid == 0) {
        float tot = 0.f;
#pragma unroll
        for (int k = 0; k < 8; k++) tot += red[k];
        red[0] = rsqrtf(tot * (1.f / 1024.f) + 1e-5f);
    }
    __syncthreads();
    const float rstd = red[0];
    for (int j = tid; j < 1024; j += 256)
        out[t * 1024 + j] = (xs[j] - mu) * rstd * gamma[j] + beta[j];
}

// ---------------------------------------------------------------------------
// Orchestration
// ---------------------------------------------------------------------------
extern "C" void kernel_launch(void* const* d_in, const int* in_sizes, int n_in,
                              void* d_out, int out_size)
{
    (void)in_sizes; (void)n_in; (void)out_size;
    const float* w     = (const float*)d_in[0];
    const float* r     = (const float*)d_in[1];
    const float* rwb   = (const float*)d_in[2];
    const float* rrb   = (const float*)d_in[3];
    const float* Wqkv  = (const float*)d_in[4];
    const float* Wr    = (const float*)d_in[5];
    const float* Wo    = (const float*)d_in[6];
    const float* cwq   = (const float*)d_in[7];
    const float* cbq   = (const float*)d_in[8];
    const float* cwk   = (const float*)d_in[9];
    const float* cbk   = (const float*)d_in[10];
    const float* cwv   = (const float*)d_in[11];
    const float* cbv   = (const float*)d_in[12];
    const float* gamma = (const float*)d_in[13];
    const float* beta  = (const float*)d_in[14];
    // d_in[15] = attn_mask (deterministic causal; recomputed in-kernel)
    float* out = (float*)d_out;

    float *heads, *convin, *rproj, *rhk, *qw, *qr, *kh, *vh, *ac, *bd, *vec, *attn, *wpad;
    cudaGetSymbolAddress((void**)&heads,  g_heads);
    cudaGetSymbolAddress((void**)&convin, g_convin);
    cudaGetSymbolAddress((void**)&rproj,  g_rproj);
    cudaGetSymbolAddress((void**)&rhk,    g_rhk);
    cudaGetSymbolAddress((void**)&qw,     g_qw);
    cudaGetSymbolAddress((void**)&qr,     g_qr);
    cudaGetSymbolAddress((void**)&kh,     g_kh);
    cudaGetSymbolAddress((void**)&vh,     g_vh);
    cudaGetSymbolAddress((void**)&ac,     g_ac);
    cudaGetSymbolAddress((void**)&bd,     g_bd);
    cudaGetSymbolAddress((void**)&vec,    g_vec);
    cudaGetSymbolAddress((void**)&attn,   g_attn);
    cudaGetSymbolAddress((void**)&wpad,   g_wpad);

    // 1. heads[4096][3072] = w[4096][1024] @ Wqkv[3072][1024]^T
    gemm_k<128,128,8,8,8,false,false,0><<<dim3(24, 32, 1), 256>>>(
        w, Wqkv, heads, 1024, 1024, 1024, 3072, 0, 0, 0, 0);

    // 2. rproj[1024][1024] = r @ Wr^T
    gemm_k<128,128,8,8,8,false,false,0><<<dim3(8, 8, 1), 256>>>(
        r, Wr, rproj, 1024, 1024, 1024, 1024, 0, 0, 0, 0);

    // 3. layout transposes
    transpose_heads_k<<<dim3(32, 96, 4), dim3(32, 8)>>>(heads, convin);
    transpose_r_k<<<dim3(32, 32), dim3(32, 8)>>>(rproj, rhk);

    // 4. conv weight padding + conv (fused conv-bias and r_w/r_r bias adds)
    prep_w_k<<<(3 * 64 * 64 * 8 + 255) / 256, 256>>>(cwq, cwk, cwv, wpad);
    conv_k<<<dim3(8, 64, 3), 256>>>(convin, wpad, cbq, cbk, cbv, rwb, rrb,
                                    qw, qr, kh, vh);

    // 5. AC[z][i][j] = sum_d qw[z][d][i] * kh[z][d][j]   (batched TN, K=64)
    gemm_k<128,128,8,8,8,true,true,0><<<dim3(8, 8, 64), 256>>>(
        qw, kh, ac, 64, 1024, 1024, 1024, 65536L, 65536L, 0, 1048576L);

    // 6. BDraw[z][i][m] = sum_d qr[z][d][i] * rhk[h][d][m]
    gemm_k<128,128,8,8,8,true,true,0><<<dim3(8, 8, 64), 256>>>(
        qr, rhk, bd, 64, 1024, 1024, 1024, 65536L, 65536L, 1, 1048576L);

    // 7. fused rel-shift + causal mask + softmax -> prob (in-place in ac)
    softmax_k<<<dim3(1024, 64), 256>>>(ac, bd);

    // 8. vec[i*4+b][h*64+d] = sum_j prob[z][i][j] * vh[z][d][j]
    gemm_k<128,64,8,8,4,false,false,1><<<dim3(1, 8, 64), 256>>>(
        ac, vh, vec, 1024, 1024, 1024, 4096, 1048576L, 65536L, 0, 0);

    // 9. attn[4096][1024] = vec @ Wo^T
    gemm_k<128,128,8,8,8,false,false,0><<<dim3(8, 32, 1), 256>>>(
        vec, Wo, attn, 1024, 1024, 1024, 1024, 0, 0, 0, 0);

    // 10. out = LayerNorm(w + attn)
    ln_k<<<4096, 256>>>(w, attn, gamma, beta, out);
}

// round 9
// speedup vs baseline: 1.2203x; 1.2203x over previous
#include <cuda_runtime.h>

// ---------------------------------------------------------------------------
// Problem constants
// ---------------------------------------------------------------------------
#define QLEN  1024
#define BSZ   4
#define NH    16
#define DH    64
#define DM    1024
#define NTOK  4096          // QLEN*BSZ
#define NBH   64            // NH*BSZ  (batch index z = h*4 + b)
#define ATT_SCALE 0.125f    // 1/sqrt(64)

// ---------------------------------------------------------------------------
// Device scratch
// ---------------------------------------------------------------------------
__device__ float g_heads [(long)NTOK * 3072];
__device__ float g_convin[(long)3 * NBH * DH * QLEN];
__device__ float g_rproj [(long)QLEN * DM];
__device__ float g_rhk   [(long)DM * QLEN];
__device__ float g_qw    [(long)NBH * DH * QLEN];
__device__ float g_qr    [(long)NBH * DH * QLEN];
__device__ float g_kh    [(long)NBH * DH * QLEN];
__device__ float g_vh    [(long)NBH * DH * QLEN];
__device__ float g_ac    [(long)NBH * QLEN * QLEN];   // becomes prob
__device__ float g_bd    [(long)NBH * QLEN * QLEN];
__device__ float g_vec   [(long)NTOK * DM];
__device__ float g_attn  [(long)NTOK * DM];
__device__ float g_wpad  [3 * DH * DH * 8];

// ---------------------------------------------------------------------------
// Double-buffered batched SGEMM: C[m][n] = sum_k A(k,m)*B(k,n)
//   AT : A stored [K][M] (M contiguous) ; !AT : A stored [M][K]
//   CMODE 0: C = Cb + z*cStride ; CMODE 1: PV scatter layout.
//   MASK  0: none
//         1: AC causal  -- skip block if n0 > m0+BM-1
//         2: BD band    -- skip block if m0+n0+BM+BN <= 1024 (never read)
//         3: PV K-bound -- K = min(K, m0+BM)  (prob zero beyond diagonal)
// ---------------------------------------------------------------------------
template<int BM,int BN,int BK,int TM,int TN,bool AT,bool BT,int CMODE,int MASK>
__global__ __launch_bounds__((BM/TM)*(BN/TN))
void gemm_k(const float* __restrict__ Ab, const float* __restrict__ Bb,
            float* __restrict__ Cb,
            int K, int lda, int ldb, int ldc,
            long aStride, long bStride, int bShift, long cStride)
{
    constexpr int TX = BN / TN;
    constexpr int TY = BM / TM;
    constexpr int NT = TX * TY;
    constexpr int NA = BM * BK / 4;     // float4s per A tile
    constexpr int NB = BN * BK / 4;
    constexpr int LA = (NA + NT - 1) / NT;
    constexpr int LB = (NB + NT - 1) / NT;

    const int tid = threadIdx.x;
    const int z   = blockIdx.z;
    const int m0  = blockIdx.y * BM;
    const int n0  = blockIdx.x * BN;

    if (MASK == 1 && n0 > m0 + BM - 1) return;
    if (MASK == 2 && m0 + n0 + BM + BN <= 1024) return;
    if (MASK == 3) K = (K < m0 + BM) ? K : (m0 + BM);

    const float* A = Ab + (long)z * aStride;
    const float* B = Bb + (long)(bShift ? (z >> 2) : z) * bStride;
    float* C;
    if (CMODE == 0) C = Cb + (long)z * cStride;
    else            C = Cb + (long)(z & 3) * 1024 + (long)(z >> 2) * 64;

    __shared__ float As[2][BK][BM + 4];
    __shared__ float Bs[2][BK][BN + 4];

    const int tx = tid % TX;
    const int ty = tid / TX;

    float acc[TM][TN];
#pragma unroll
    for (int i = 0; i < TM; i++)
#pragma unroll
        for (int j = 0; j < TN; j++) acc[i][j] = 0.f;

    float4 ra[LA], rb[LB];

#define LOAD_A(K0)                                                             \
    _Pragma("unroll")                                                          \
    for (int u = 0; u < LA; u++) {                                             \
        int i = tid + u * NT;                                                  \
        if (NA % NT == 0 || i < NA) {                                          \
            if (AT) { int r = i / (BM/4), c = i % (BM/4);                      \
                ra[u] = *(const float4*)(A + (long)((K0) + r) * lda + m0 + c*4); } \
            else    { int r = i / (BK/4), q = i % (BK/4);                      \
                ra[u] = *(const float4*)(A + (long)(m0 + r) * lda + (K0) + q*4); } \
        }                                                                      \
    }
#define LOAD_B(K0)                                                             \
    _Pragma("unroll")                                                          \
    for (int u = 0; u < LB; u++) {                                             \
        int i = tid + u * NT;                                                  \
        if (NB % NT == 0 || i < NB) {                                          \
            if (BT) { int r = i / (BN/4), c = i % (BN/4);                      \
                rb[u] = *(const float4*)(B + (long)((K0) + r) * ldb + n0 + c*4); } \
            else    { int r = i / (BK/4), q = i % (BK/4);                      \
                rb[u] = *(const float4*)(B + (long)(n0 + r) * ldb + (K0) + q*4); } \
        }                                                                      \
    }
#define STORE_A(BUF)                                                           \
    _Pragma("unroll")                                                          \
    for (int u = 0; u < LA; u++) {                                             \
        int i = tid + u * NT;                                                  \
        if (NA % NT == 0 || i < NA) {                                          \
            if (AT) { int r = i / (BM/4), c = i % (BM/4);                      \
                *(float4*)&As[BUF][r][c*4] = ra[u]; }                          \
            else    { int r = i / (BK/4), q = i % (BK/4);                      \
                As[BUF][q*4+0][r] = ra[u].x; As[BUF][q*4+1][r] = ra[u].y;      \
                As[BUF][q*4+2][r] = ra[u].z; As[BUF][q*4+3][r] = ra[u].w; }    \
        }                                                                      \
    }
#define STORE_B(BUF)                                                           \
    _Pragma("unroll")                                                          \
    for (int u = 0; u < LB; u++) {                                             \
        int i = tid + u * NT;                                                  \
        if (NB % NT == 0 || i < NB) {                                          \
            if (BT) { int r = i / (BN/4), c = i % (BN/4);                      \
                *(float4*)&Bs[BUF][r][c*4] = rb[u]; }                          \
            else    { int r = i / (BK/4), q = i % (BK/4);                      \
                Bs[BUF][q*4+0][r] = rb[u].x; Bs[BUF][q*4+1][r] = rb[u].y;      \
                Bs[BUF][q*4+2][r] = rb[u].z; Bs[BUF][q*4+3][r] = rb[u].w; }    \
        }                                                                      \
    }

    // Prologue: tile 0 -> buffer 0
    LOAD_A(0)
    LOAD_B(0)
    STORE_A(0)
    STORE_B(0)
    __syncthreads();

    const int ktiles = K / BK;
    for (int t = 0; t < ktiles; t++) {
        const int cur = t & 1;
        if (t + 1 < ktiles) {
            const int nk = (t + 1) * BK;
            LOAD_A(nk)
            LOAD_B(nk)
        }
#pragma unroll
        for (int kk = 0; kk < BK; kk++) {
            float a[TM], b[TN];
#pragma unroll
            for (int u = 0; u < TM / 4; u++)
                *(float4*)&a[u * 4] = *(const float4*)&As[cur][kk][ty * TM + u * 4];
#pragma unroll
            for (int u = 0; u < TN / 4; u++)
                *(float4*)&b[u * 4] = *(const float4*)&Bs[cur][kk][tx * TN + u * 4];
#pragma unroll
            for (int i = 0; i < TM; i++)
#pragma unroll
                for (int j = 0; j < TN; j++)
                    acc[i][j] += a[i] * b[j];
        }
        if (t + 1 < ktiles) {
            const int nxt = cur ^ 1;
            STORE_A(nxt)
            STORE_B(nxt)
            __syncthreads();
        }
    }

#pragma unroll
    for (int i = 0; i < TM; i++) {
        long row = m0 + ty * TM + i;
#pragma unroll
        for (int u = 0; u < TN / 4; u++) {
            float4 v = make_float4(acc[i][u*4+0], acc[i][u*4+1],
                                   acc[i][u*4+2], acc[i][u*4+3]);
            *(float4*)(C + row * ldc + n0 + tx * TN + u * 4) = v;
        }
    }
#undef LOAD_A
#undef LOAD_B
#undef STORE_A
#undef STORE_B
}

// ---------------------------------------------------------------------------
// Transpose heads[tok=(q*4+b)][c] -> convin[s][h*4+b][d][q]
// ---------------------------------------------------------------------------
__global__ void transpose_heads_k(const float* __restrict__ heads,
                                  float* __restrict__ convin)
{
    __shared__ float tile[32][33];
    const int q0 = blockIdx.x * 32;
    const int c0 = blockIdx.y * 32;
    const int b  = blockIdx.z;
    const int x = threadIdx.x, y = threadIdx.y;
#pragma unroll
    for (int yy = 0; yy < 32; yy += 8)
        tile[yy + y][x] = heads[((long)(q0 + yy + y) * 4 + b) * 3072 + c0 + x];
    __syncthreads();
#pragma unroll
    for (int yy = 0; yy < 32; yy += 8) {
        int ch = c0 + yy + y;
        int s = ch >> 10, rem = ch & 1023, h = rem >> 6, d = rem & 63;
        convin[((long)(s * 64 + h * 4 + b) * 64 + d) * 1024 + q0 + x] = tile[x][yy + y];
    }
}

__global__ void transpose_r_k(const float* __restrict__ rproj, float* __restrict__ rhk)
{
    __shared__ float tile[32][33];
    const int m0 = blockIdx.x * 32;
    const int c0 = blockIdx.y * 32;
    const int x = threadIdx.x, y = threadIdx.y;
#pragma unroll
    for (int yy = 0; yy < 32; yy += 8)
        tile[yy + y][x] = rproj[(long)(m0 + yy + y) * 1024 + c0 + x];
    __syncthreads();
#pragma unroll
    for (int yy = 0; yy < 32; yy += 8)
        rhk[(long)(c0 + yy + y) * 1024 + m0 + x] = tile[x][yy + y];
}

__global__ void prep_w_k(const float* __restrict__ wq, const float* __restrict__ wk,
                         const float* __restrict__ wv, float* __restrict__ wpad)
{
    int i = blockIdx.x * 256 + threadIdx.x;
    if (i >= 3 * 64 * 64 * 8) return;
    int t  = i & 7;
    int oi = (i >> 3) & 4095;
    int s  = i >> 15;
    const float* src = (s == 0) ? wq : (s == 1) ? wk : wv;
    wpad[i] = (t < 7) ? src[oi * 7 + t] : 0.f;
}

// ---------------------------------------------------------------------------
// Conv1d (same padding, K=7, 64x64 channel mix), fused bias epilogues.
// ---------------------------------------------------------------------------
__global__ __launch_bounds__(256)
void conv_k(const float* __restrict__ convin, const float* __restrict__ wpad,
            const float* __restrict__ cbq, const float* __restrict__ cbk,
            const float* __restrict__ cbv,
            const float* __restrict__ rwb, const float* __restrict__ rrb,
            float* __restrict__ qw, float* __restrict__ qr,
            float* __restrict__ kh, float* __restrict__ vh)
{
    const int s  = blockIdx.z;
    const int hb = blockIdx.y;
    const int l0 = blockIdx.x * 128;
    const float* x  = convin + (long)(s * 64 + hb) * (64 * 1024);
    const float* wp = wpad + (long)s * (64 * 64 * 8);

    __shared__ float xs[64][136];
    for (int i = threadIdx.x; i < 64 * 134; i += 256) {
        int din = i / 134, c = i % 134;
        int gl = l0 - 3 + c;
        xs[din][c] = (gl >= 0 && gl < 1024) ? x[(long)din * 1024 + gl] : 0.f;
    }
    __syncthreads();

    const int lsub = threadIdx.x & 31;
    const int g    = threadIdx.x >> 5;

    float acc[8][4];
#pragma unroll
    for (int o = 0; o < 8; o++)
#pragma unroll
        for (int j = 0; j < 4; j++) acc[o][j] = 0.f;

    for (int din = 0; din < 64; din++) {
        float xv[4][7];
#pragma unroll
        for (int j = 0; j < 4; j++)
#pragma unroll
            for (int t = 0; t < 7; t++)
                xv[j][t] = xs[din][lsub + 32 * j + t];
#pragma unroll
        for (int o = 0; o < 8; o++) {
            const float4* wr = (const float4*)(wp + ((g * 8 + o) * 64 + din) * 8);
            float4 wa = __ldg(wr);
            float4 wb = __ldg(wr + 1);
            float wv[7] = {wa.x, wa.y, wa.z, wa.w, wb.x, wb.y, wb.z};
#pragma unroll
            for (int t = 0; t < 7; t++)
#pragma unroll
                for (int j = 0; j < 4; j++)
                    acc[o][j] += wv[t] * xv[j][t];
        }
    }

    const int h = hb >> 2;
#pragma unroll
    for (int o = 0; o < 8; o++) {
        int dout = g * 8 + o;
        long base = ((long)hb * 64 + dout) * 1024 + l0 + lsub;
        if (s == 0) {
            float bv = cbq[dout];
            float aw = rwb[h * 64 + dout];
            float ar = rrb[h * 64 + dout];
#pragma unroll
            for (int j = 0; j < 4; j++) {
                float v = acc[o][j] + bv;
                qw[base + 32 * j] = v + aw;
                qr[base + 32 * j] = v + ar;
            }
        } else if (s == 1) {
            float bv = cbk[dout];
#pragma unroll
            for (int j = 0; j < 4; j++) kh[base + 32 * j] = acc[o][j] + bv;
        } else {
            float bv = cbv[dout];
#pragma unroll
            for (int j = 0; j < 4; j++) vh[base + 32 * j] = acc[o][j] + bv;
        }
    }
}

// ---------------------------------------------------------------------------
// Fused rel-shift + causal mask + softmax, in-place into AC (writes full rows,
// zeros above the diagonal -> downstream PV is a dense GEMM with bounded K).
// ---------------------------------------------------------------------------
__global__ __launch_bounds__(256)
void softmax_k(float* __restrict__ acbuf, const float* __restrict__ bdbuf)
{
    const int i = blockIdx.x;
    const int z = blockIdx.y;
    float* ac       = acbuf + (long)z * (1024L * 1024) + (long)i * 1024;
    const float* bd = bdbuf + (long)z * (1024L * 1024) + (long)i * 1024 + (1023 - i);
    const int n = i + 1;
    __shared__ float red[8];
    const int tid = threadIdx.x;
    const int lane = tid & 31, wid = tid >> 5;

    float mx = -1e30f;
    for (int j = tid; j < n; j += 256)
        mx = fmaxf(mx, (ac[j] + bd[j]) * ATT_SCALE);
#pragma unroll
    for (int o = 16; o > 0; o >>= 1)
        mx = fmaxf(mx, __shfl_xor_sync(0xffffffffu, mx, o));
    if (lane == 0) red[wid] = mx;
    __syncthreads();
    if (tid == 0) {
        float m = red[0];
#pragma unroll
        for (int k = 1; k < 8; k++) m = fmaxf(m, red[k]);
        red[0] = m;
    }
    __syncthreads();
    const float MX = red[0];
    __syncthreads();

    float sum = 0.f;
    for (int j = tid; j < n; j += 256) {
        float e = __expf((ac[j] + bd[j]) * ATT_SCALE - MX);
        ac[j] = e;
        sum += e;
    }
#pragma unroll
    for (int o = 16; o > 0; o >>= 1)
        sum += __shfl_xor_sync(0xffffffffu, sum, o);
    if (lane == 0) red[wid] = sum;
    __syncthreads();
    if (tid == 0) {
        float sm = 0.f;
#pragma unroll
        for (int k = 0; k < 8; k++) sm += red[k];
        red[0] = 1.f / sm;
    }
    __syncthreads();
    const float inv = red[0];
    for (int j = tid; j < 1024; j += 256)
        ac[j] = (j < n) ? ac[j] * inv : 0.f;
}

// ---------------------------------------------------------------------------
// Fused residual + LayerNorm (last dim 1024)
// ---------------------------------------------------------------------------
__global__ __launch_bounds__(256)
void ln_k(const float* __restrict__ w, const float* __restrict__ attn,
          const float* __restrict__ gamma, const float* __restrict__ beta,
          float* __restrict__ out)
{
    const long t = blockIdx.x;
    __shared__ float xs[1024];
    __shared__ float red[8];
    const int tid = threadIdx.x, lane = tid & 31, wid = tid >> 5;

    float s = 0.f;
    for (int j = tid; j < 1024; j += 256) {
        float v = w[t * 1024 + j] + attn[t * 1024 + j];
        xs[j] = v;
        s += v;
    }
#pragma unroll
    for (int o = 16; o > 0; o >>= 1) s += __shfl_xor_sync(0xffffffffu, s, o);
    if (lane == 0) red[wid] = s;
    __syncthreads();
    if (tid == 0) {
        float tot = 0.f;
#pragma unroll
        for (int k = 0; k < 8; k++) tot += red[k];
        red[0] = tot * (1.f / 1024.f);
    }
    __syncthreads();
    const float mu = red[0];
    __syncthreads();

    float vs = 0.f;
    for (int j = tid; j < 1024; j += 256) {
        float d = xs[j] - mu;
        vs += d * d;
    }
#pragma unroll
    for (int o = 16; o > 0; o >>= 1) vs += __shfl_xor_sync(0xffffffffu, vs, o);
    if (lane == 0) red[wid] = vs;
    __syncthreads();
    if (tid == 0) {
        float tot = 0.f;
#pragma unroll
        for (int k = 0; k < 8; k++) tot += red[k];
        red[0] = rsqrtf(tot * (1.f / 1024.f) + 1e-5f);
    }
    __syncthreads();
    const float rstd = red[0];
    for (int j = tid; j < 1024; j += 256)
        out[t * 1024 + j] = (xs[j] - mu) * rstd * gamma[j] + beta[j];
}

// ---------------------------------------------------------------------------
// Orchestration
// ---------------------------------------------------------------------------
extern "C" void kernel_launch(void* const* d_in, const int* in_sizes, int n_in,
                              void* d_out, int out_size)
{
    (void)in_sizes; (void)n_in; (void)out_size;
    const float* w     = (const float*)d_in[0];
    const float* r     = (const float*)d_in[1];
    const float* rwb   = (const float*)d_in[2];
    const float* rrb   = (const float*)d_in[3];
    const float* Wqkv  = (const float*)d_in[4];
    const float* Wr    = (const float*)d_in[5];
    const float* Wo    = (const float*)d_in[6];
    const float* cwq   = (const float*)d_in[7];
    const float* cbq   = (const float*)d_in[8];
    const float* cwk   = (const float*)d_in[9];
    const float* cbk   = (const float*)d_in[10];
    const float* cwv   = (const float*)d_in[11];
    const float* cbv   = (const float*)d_in[12];
    const float* gamma = (const float*)d_in[13];
    const float* beta  = (const float*)d_in[14];
    float* out = (float*)d_out;

    float *heads, *convin, *rproj, *rhk, *qw, *qr, *kh, *vh, *ac, *bd, *vec, *attn, *wpad;
    cudaGetSymbolAddress((void**)&heads,  g_heads);
    cudaGetSymbolAddress((void**)&convin, g_convin);
    cudaGetSymbolAddress((void**)&rproj,  g_rproj);
    cudaGetSymbolAddress((void**)&rhk,    g_rhk);
    cudaGetSymbolAddress((void**)&qw,     g_qw);
    cudaGetSymbolAddress((void**)&qr,     g_qr);
    cudaGetSymbolAddress((void**)&kh,     g_kh);
    cudaGetSymbolAddress((void**)&vh,     g_vh);
    cudaGetSymbolAddress((void**)&ac,     g_ac);
    cudaGetSymbolAddress((void**)&bd,     g_bd);
    cudaGetSymbolAddress((void**)&vec,    g_vec);
    cudaGetSymbolAddress((void**)&attn,   g_attn);
    cudaGetSymbolAddress((void**)&wpad,   g_wpad);

    // 1. heads = w @ Wqkv^T
    gemm_k<128,128,8,8,8,false,false,0,0><<<dim3(24, 32, 1), 256>>>(
        w, Wqkv, heads, 1024, 1024, 1024, 3072, 0, 0, 0, 0);

    // 2. rproj = r @ Wr^T
    gemm_k<128,128,8,8,8,false,false,0,0><<<dim3(8, 8, 1), 256>>>(
        r, Wr, rproj, 1024, 1024, 1024, 1024, 0, 0, 0, 0);

    // 3. layout transposes
    transpose_heads_k<<<dim3(32, 96, 4), dim3(32, 8)>>>(heads, convin);
    transpose_r_k<<<dim3(32, 32), dim3(32, 8)>>>(rproj, rhk);

    // 4. conv weight padding + conv (fused conv-bias and r_w/r_r bias adds)
    prep_w_k<<<(3 * 64 * 64 * 8 + 255) / 256, 256>>>(cwq, cwk, cwv, wpad);
    conv_k<<<dim3(8, 64, 3), 256>>>(convin, wpad, cbq, cbk, cbv, rwb, rrb,
                                    qw, qr, kh, vh);

    // 5. AC (causal: upper-triangular blocks skipped; softmax zero-fills them)
    gemm_k<128,128,8,8,8,true,true,0,1><<<dim3(8, 8, 64), 256>>>(
        qw, kh, ac, 64, 1024, 1024, 1024, 65536L, 65536L, 0, 1048576L);

    // 6. BDraw (band: blocks never read by the shifted softmax are skipped)
    gemm_k<128,128,8,8,8,true,true,0,2><<<dim3(8, 8, 64), 256>>>(
        qr, rhk, bd, 64, 1024, 1024, 1024, 65536L, 65536L, 1, 1048576L);

    // 7. fused rel-shift + causal mask + softmax -> prob (in-place in ac)
    softmax_k<<<dim3(1024, 64), 256>>>(ac, bd);

    // 8. PV with causal K-bound (prob is zero above the diagonal)
    gemm_k<128,64,8,8,4,false,false,1,3><<<dim3(1, 8, 64), 256>>>(
        ac, vh, vec, 1024, 1024, 1024, 4096, 1048576L, 65536L, 0, 0);

    // 9. attn = vec @ Wo^T
    gemm_k<128,128,8,8,8,false,false,0,0><<<dim3(8, 32, 1), 256>>>(
        vec, Wo, attn, 1024, 1024, 1024, 1024, 0, 0, 0, 0);

    // 10. out = LayerNorm(w + attn)
    ln_k<<<4096, 256>>>(w, attn, gamma, beta, out);
}

// round 12
// speedup vs baseline: 1.5280x; 1.2522x over previous
#include <cuda_runtime.h>
#include <cuda_bf16.h>
#include <cstdint>

// ---------------------------------------------------------------------------
// Problem constants
// ---------------------------------------------------------------------------
#define QLEN  1024
#define BSZ   4
#define NH    16
#define DH    64
#define DM    1024
#define NTOK  4096
#define NBH   64
#define ATT_SCALE 0.125f

// ---------------------------------------------------------------------------
// Device scratch
// ---------------------------------------------------------------------------
__device__ float g_heads [(long)NTOK * 3072];
__device__ float g_convin[(long)3 * NBH * DH * QLEN];
__device__ float g_rproj [(long)QLEN * DM];
__device__ float g_rhk   [(long)DM * QLEN];
__device__ float g_qw    [(long)NBH * DH * QLEN];
__device__ float g_qr    [(long)NBH * DH * QLEN];
__device__ float g_kh    [(long)NBH * DH * QLEN];
__device__ float g_vh    [(long)NBH * DH * QLEN];
__device__ float g_ac    [(long)NBH * QLEN * QLEN];
__device__ float g_bd    [(long)NBH * QLEN * QLEN];
__device__ float g_vec   [(long)NTOK * DM];
__device__ float g_attn  [(long)NTOK * DM];
__device__ float g_wpad  [3 * DH * DH * 8];

// Split-bf16 operands for the tensor-core GEMMs (plain row-major [rows][1024])
__device__ __nv_bfloat16 g_ahi[(long)4096 * 1024];
__device__ __nv_bfloat16 g_alo[(long)4096 * 1024];
__device__ __nv_bfloat16 g_bhi[(long)3072 * 1024];
__device__ __nv_bfloat16 g_blo[(long)3072 * 1024];
__device__ __nv_bfloat16 g_whi[(long)1024 * 1024];
__device__ __nv_bfloat16 g_wlo[(long)1024 * 1024];

// ---------------------------------------------------------------------------
// Baseline-PTX helpers (all valid on plain sm_103: no 'a'-gated features)
// ---------------------------------------------------------------------------
__device__ __forceinline__ uint32_t s2u(const void* p) {
    uint32_t a;
    asm("{ .reg .u64 t; cvta.to.shared.u64 t, %1; cvt.u32.u64 %0, t; }"
        : "=r"(a) : "l"(p));
    return a;
}
__device__ __forceinline__ void cpasync16(uint32_t dst, const void* src) {
    asm volatile("cp.async.cg.shared.global [%0], [%1], 16;" :: "r"(dst), "l"(src));
}
__device__ __forceinline__ void cp_commit() {
    asm volatile("cp.async.commit_group;" ::: "memory");
}
__device__ __forceinline__ void ldsm4(uint32_t* r, uint32_t a) {
    asm volatile("ldmatrix.sync.aligned.m8n8.x4.shared.b16 {%0,%1,%2,%3}, [%4];"
                 : "=r"(r[0]), "=r"(r[1]), "=r"(r[2]), "=r"(r[3]) : "r"(a));
}
__device__ __forceinline__ void mma16816(float* c, const uint32_t* a, const uint32_t* b) {
    asm volatile(
        "mma.sync.aligned.m16n8k16.row.col.f32.bf16.bf16.f32 "
        "{%0,%1,%2,%3}, {%4,%5,%6,%7}, {%8,%9}, {%0,%1,%2,%3};"
        : "+f"(c[0]), "+f"(c[1]), "+f"(c[2]), "+f"(c[3])
        : "r"(a[0]), "r"(a[1]), "r"(a[2]), "r"(a[3]), "r"(b[0]), "r"(b[1]));
}

// ---------------------------------------------------------------------------
// Pack fp32 [rows][1024] -> hi/lo bf16 row-major (split compensation operands)
// ---------------------------------------------------------------------------
__global__ __launch_bounds__(256)
void pack2_k(const float* __restrict__ X, __nv_bfloat16* __restrict__ Hi,
             __nv_bfloat16* __restrict__ Lo, int n4)
{
    int i = blockIdx.x * 256 + threadIdx.x;
    if (i >= n4) return;
    float4 v = ((const float4*)X)[i];
    float vv[4] = {v.x, v.y, v.z, v.w};
    unsigned short hs[4], ls[4];
#pragma unroll
    for (int j = 0; j < 4; j++) {
        __nv_bfloat16 h = __float2bfloat16(vv[j]);
        __nv_bfloat16 l = __float2bfloat16(vv[j] - __bfloat162float(h));
        hs[j] = *reinterpret_cast<unsigned short*>(&h);
        ls[j] = *reinterpret_cast<unsigned short*>(&l);
    }
    uint2 uh = make_uint2((uint32_t)hs[0] | ((uint32_t)hs[1] << 16),
                          (uint32_t)hs[2] | ((uint32_t)hs[3] << 16));
    uint2 ul = make_uint2((uint32_t)ls[0] | ((uint32_t)ls[1] << 16),
                          (uint32_t)ls[2] | ((uint32_t)ls[3] << 16));
    *(uint2*)(Hi + 4L * i) = uh;
    *(uint2*)(Lo + 4L * i) = ul;
}

// ---------------------------------------------------------------------------
// Tensor-core GEMM via mma.sync (HMMA fallback path — the only tensor path
// reachable under the harness's compute_103 virtual arch).
// C[m][n] = sum_k A[m][k]*B[n][k], A/B given as (hi,lo) bf16, 3-MMA split.
// 128x128 block, 8 warps (4x2), warp tile 32x64, BK=32, cp.async 2-stage.
// ---------------------------------------------------------------------------
#define SROW 40                         // halves per smem row (80B: conflict-free ldmatrix)
#define MATB (128 * SROW * 2)           // 10240 B per matrix tile
#define STGB (4 * MATB)                 // stage: Ahi,Alo,Bhi,Blo

__global__ __launch_bounds__(256)
void mma_gemm_k(const __nv_bfloat16* __restrict__ Ah, const __nv_bfloat16* __restrict__ Al,
                const __nv_bfloat16* __restrict__ Bh, const __nv_bfloat16* __restrict__ Bl,
                float* __restrict__ C, int ldc, int K)
{
    extern __shared__ __align__(16) unsigned char sm_raw[];
    const uint32_t sb = s2u(sm_raw);
    const int tid = threadIdx.x, lane = tid & 31, wid = tid >> 5;
    const int m0 = blockIdx.y * 128, n0 = blockIdx.x * 128;
    const int wm = wid & 3, wn = wid >> 2;

    const int lr = tid >> 2;     // loader row base (0..63)
    const int lc = tid & 3;      // loader 16B chunk (0..3)

    float acc[2][8][4];
#pragma unroll
    for (int a = 0; a < 2; a++)
#pragma unroll
        for (int b = 0; b < 8; b++)
#pragma unroll
            for (int d = 0; d < 4; d++) acc[a][b][d] = 0.f;

#define STAGE_LOAD(T, BUF)                                                    \
    {                                                                         \
        uint32_t s0 = sb + (BUF) * STGB;                                      \
        int k0 = (T) * 32;                                                    \
        _Pragma("unroll")                                                     \
        for (int it = 0; it < 2; it++) {                                      \
            int row = lr + it * 64;                                           \
            uint32_t so = (uint32_t)(row * SROW + lc * 8) * 2;                \
            long ga = (long)(m0 + row) * K + k0 + lc * 8;                     \
            long gb = (long)(n0 + row) * K + k0 + lc * 8;                     \
            cpasync16(s0 + so,            Ah + ga);                           \
            cpasync16(s0 + MATB + so,     Al + ga);                           \
            cpasync16(s0 + 2 * MATB + so, Bh + gb);                           \
            cpasync16(s0 + 3 * MATB + so, Bl + gb);                           \
        }                                                                     \
    }

    STAGE_LOAD(0, 0)
    cp_commit();

    const int T = K / 32;
    for (int t = 0; t < T; t++) {
        const int cur = t & 1;
        if (t + 1 < T) {
            STAGE_LOAD(t + 1, cur ^ 1)
            cp_commit();
            asm volatile("cp.async.wait_group 1;" ::: "memory");
        } else {
            asm volatile("cp.async.wait_group 0;" ::: "memory");
        }
        __syncthreads();

        const uint32_t s0 = sb + cur * STGB;
#pragma unroll
        for (int ks = 0; ks < 2; ks++) {
            const int k0 = ks * 16;
            uint32_t ah[2][4], al[2][4], bh[4][4], bl[4][4];
#pragma unroll
            for (int mt = 0; mt < 2; mt++) {
                int row = wm * 32 + mt * 16 + (lane & 15);
                int col = k0 + ((lane >> 4) << 3);
                uint32_t ao = (uint32_t)(row * SROW + col) * 2;
                ldsm4(ah[mt], s0 + ao);
                ldsm4(al[mt], s0 + MATB + ao);
            }
#pragma unroll
            for (int p = 0; p < 4; p++) {
                int row = wn * 64 + p * 16 + ((lane >> 4) << 3) + (lane & 7);
                int col = k0 + (((lane >> 3) & 1) << 3);
                uint32_t bo = (uint32_t)(row * SROW + col) * 2;
                ldsm4(bh[p], s0 + 2 * MATB + bo);
                ldsm4(bl[p], s0 + 3 * MATB + bo);
            }
            // hi*hi
#pragma unroll
            for (int mt = 0; mt < 2; mt++)
#pragma unroll
                for (int nt = 0; nt < 8; nt++)
                    mma16816(acc[mt][nt], ah[mt], &bh[nt >> 1][(nt & 1) * 2]);
            // hi*lo
#pragma unroll
            for (int mt = 0; mt < 2; mt++)
#pragma unroll
                for (int nt = 0; nt < 8; nt++)
                    mma16816(acc[mt][nt], ah[mt], &bl[nt >> 1][(nt & 1) * 2]);
            // lo*hi
#pragma unroll
            for (int mt = 0; mt < 2; mt++)
#pragma unroll
                for (int nt = 0; nt < 8; nt++)
                    mma16816(acc[mt][nt], al[mt], &bh[nt >> 1][(nt & 1) * 2]);
        }
        __syncthreads();
    }

#pragma unroll
    for (int mt = 0; mt < 2; mt++) {
        int row = m0 + wm * 32 + mt * 16 + (lane >> 2);
#pragma unroll
        for (int nt = 0; nt < 8; nt++) {
            int col = n0 + wn * 64 + nt * 8 + (lane & 3) * 2;
            *(float2*)(C + (long)row * ldc + col) =
                make_float2(acc[mt][nt][0], acc[mt][nt][1]);
            *(float2*)(C + (long)(row + 8) * ldc + col) =
                make_float2(acc[mt][nt][2], acc[mt][nt][3]);
        }
    }
#undef STAGE_LOAD
}

// ---------------------------------------------------------------------------
// SIMT double-buffered batched SGEMM (rproj / AC / BD / PV)
// ---------------------------------------------------------------------------
template<int BM,int BN,int BK,int TM,int TN,bool AT,bool BT,int CMODE,int MASK>
__global__ __launch_bounds__((BM/TM)*(BN/TN))
void gemm_k(const float* __restrict__ Ab, const float* __restrict__ Bb,
            float* __restrict__ Cb,
            int K, int lda, int ldb, int ldc,
            long aStride, long bStride, int bShift, long cStride)
{
    constexpr int TX = BN / TN;
    constexpr int TY = BM / TM;
    constexpr int NT = TX * TY;
    constexpr int NA = BM * BK / 4;
    constexpr int NB = BN * BK / 4;
    constexpr int LA = (NA + NT - 1) / NT;
    constexpr int LB = (NB + NT - 1) / NT;

    const int tid = threadIdx.x;
    const int z   = blockIdx.z;
    const int m0  = blockIdx.y * BM;
    const int n0  = blockIdx.x * BN;

    if (MASK == 1 && n0 > m0 + BM - 1) return;
    if (MASK == 2 && m0 + n0 + BM + BN <= 1024) return;
    if (MASK == 3) K = (K < m0 + BM) ? K : (m0 + BM);

    const float* A = Ab + (long)z * aStride;
    const float* B = Bb + (long)(bShift ? (z >> 2) : z) * bStride;
    float* C;
    if (CMODE == 0) C = Cb + (long)z * cStride;
    else            C = Cb + (long)(z & 3) * 1024 + (long)(z >> 2) * 64;

    __shared__ float As[2][BK][BM + 4];
    __shared__ float Bs[2][BK][BN + 4];

    const int tx = tid % TX;
    const int ty = tid / TX;

    float acc[TM][TN];
#pragma unroll
    for (int i = 0; i < TM; i++)
#pragma unroll
        for (int j = 0; j < TN; j++) acc[i][j] = 0.f;

    float4 ra[LA], rb[LB];

#define LOAD_A(K0)                                                             \
    _Pragma("unroll")                                                          \
    for (int u = 0; u < LA; u++) {                                             \
        int i = tid + u * NT;                                                  \
        if (NA % NT == 0 || i < NA) {                                          \
            if (AT) { int r = i / (BM/4), c = i % (BM/4);                      \
                ra[u] = *(const float4*)(A + (long)((K0) + r) * lda + m0 + c*4); } \
            else    { int r = i / (BK/4), q = i % (BK/4);                      \
                ra[u] = *(const float4*)(A + (long)(m0 + r) * lda + (K0) + q*4); } \
        }                                                                      \
    }
#define LOAD_B(K0)                                                             \
    _Pragma("unroll")                                                          \
    for (int u = 0; u < LB; u++) {                                             \
        int i = tid + u * NT;                                                  \
        if (NB % NT == 0 || i < NB) {                                          \
            if (BT) { int r = i / (BN/4), c = i % (BN/4);                      \
                rb[u] = *(const float4*)(B + (long)((K0) + r) * ldb + n0 + c*4); } \
            else    { int r = i / (BK/4), q = i % (BK/4);                      \
                rb[u] = *(const float4*)(B + (long)(n0 + r) * ldb + (K0) + q*4); } \
        }                                                                      \
    }
#define STORE_A(BUF)                                                           \
    _Pragma("unroll")                                                          \
    for (int u = 0; u < LA; u++) {                                             \
        int i = tid + u * NT;                                                  \
        if (NA % NT == 0 || i < NA) {                                          \
            if (AT) { int r = i / (BM/4), c = i % (BM/4);                      \
                *(float4*)&As[BUF][r][c*4] = ra[u]; }                          \
            else    { int r = i / (BK/4), q = i % (BK/4);                      \
                As[BUF][q*4+0][r] = ra[u].x; As[BUF][q*4+1][r] = ra[u].y;      \
                As[BUF][q*4+2][r] = ra[u].z; As[BUF][q*4+3][r] = ra[u].w; }    \
        }                                                                      \
    }
#define STORE_B(BUF)                                                           \
    _Pragma("unroll")                                                          \
    for (int u = 0; u < LB; u++) {                                             \
        int i = tid + u * NT;                                                  \
        if (NB % NT == 0 || i < NB) {                                          \
            if (BT) { int r = i / (BN/4), c = i % (BN/4);                      \
                *(float4*)&Bs[BUF][r][c*4] = rb[u]; }                          \
            else    { int r = i / (BK/4), q = i % (BK/4);                      \
                Bs[BUF][q*4+0][r] = rb[u].x; Bs[BUF][q*4+1][r] = rb[u].y;      \
                Bs[BUF][q*4+2][r] = rb[u].z; Bs[BUF][q*4+3][r] = rb[u].w; }    \
        }                                                                      \
    }

    LOAD_A(0)
    LOAD_B(0)
    STORE_A(0)
    STORE_B(0)
    __syncthreads();

    const int ktiles = K / BK;
    for (int t = 0; t < ktiles; t++) {
        const int cur = t & 1;
        if (t + 1 < ktiles) {
            const int nk = (t + 1) * BK;
            LOAD_A(nk)
            LOAD_B(nk)
        }
#pragma unroll
        for (int kk = 0; kk < BK; kk++) {
            float a[TM], b[TN];
#pragma unroll
            for (int u = 0; u < TM / 4; u++)
                *(float4*)&a[u * 4] = *(const float4*)&As[cur][kk][ty * TM + u * 4];
#pragma unroll
            for (int u = 0; u < TN / 4; u++)
                *(float4*)&b[u * 4] = *(const float4*)&Bs[cur][kk][tx * TN + u * 4];
#pragma unroll
            for (int i = 0; i < TM; i++)
#pragma unroll
                for (int j = 0; j < TN; j++)
                    acc[i][j] += a[i] * b[j];
        }
        if (t + 1 < ktiles) {
            const int nxt = cur ^ 1;
            STORE_A(nxt)
            STORE_B(nxt)
            __syncthreads();
        }
    }

#pragma unroll
    for (int i = 0; i < TM; i++) {
        long row = m0 + ty * TM + i;
#pragma unroll
        for (int u = 0; u < TN / 4; u++) {
            float4 v = make_float4(acc[i][u*4+0], acc[i][u*4+1],
                                   acc[i][u*4+2], acc[i][u*4+3]);
            *(float4*)(C + row * ldc + n0 + tx * TN + u * 4) = v;
        }
    }
#undef LOAD_A
#undef LOAD_B
#undef STORE_A
#undef STORE_B
}

// ---------------------------------------------------------------------------
// Transposes / conv prep
// ---------------------------------------------------------------------------
__global__ void transpose_heads_k(const float* __restrict__ heads,
                                  float* __restrict__ convin)
{
    __shared__ float tile[32][33];
    const int q0 = blockIdx.x * 32;
    const int c0 = blockIdx.y * 32;
    const int b  = blockIdx.z;
    const int x = threadIdx.x, y = threadIdx.y;
#pragma unroll
    for (int yy = 0; yy < 32; yy += 8)
        tile[yy + y][x] = heads[((long)(q0 + yy + y) * 4 + b) * 3072 + c0 + x];
    __syncthreads();
#pragma unroll
    for (int yy = 0; yy < 32; yy += 8) {
        int ch = c0 + yy + y;
        int s = ch >> 10, rem = ch & 1023, h = rem >> 6, d = rem & 63;
        convin[((long)(s * 64 + h * 4 + b) * 64 + d) * 1024 + q0 + x] = tile[x][yy + y];
    }
}

__global__ void transpose_r_k(const float* __restrict__ rproj, float* __restrict__ rhk)
{
    __shared__ float tile[32][33];
    const int m0 = blockIdx.x * 32;
    const int c0 = blockIdx.y * 32;
    const int x = threadIdx.x, y = threadIdx.y;
#pragma unroll
    for (int yy = 0; yy < 32; yy += 8)
        tile[yy + y][x] = rproj[(long)(m0 + yy + y) * 1024 + c0 + x];
    __syncthreads();
#pragma unroll
    for (int yy = 0; yy < 32; yy += 8)
        rhk[(long)(c0 + yy + y) * 1024 + m0 + x] = tile[x][yy + y];
}

__global__ void prep_w_k(const float* __restrict__ wq, const float* __restrict__ wk,
                         const float* __restrict__ wv, float* __restrict__ wpad)
{
    int i = blockIdx.x * 256 + threadIdx.x;
    if (i >= 3 * 64 * 64 * 8) return;
    int t  = i & 7;
    int oi = (i >> 3) & 4095;
    int s  = i >> 15;
    const float* src = (s == 0) ? wq : (s == 1) ? wk : wv;
    wpad[i] = (t < 7) ? src[oi * 7 + t] : 0.f;
}

// ---------------------------------------------------------------------------
// Conv1d + fused bias epilogues
// ---------------------------------------------------------------------------
__global__ __launch_bounds__(256)
void conv_k(const float* __restrict__ convin, const float* __restrict__ wpad,
            const float* __restrict__ cbq, const float* __restrict__ cbk,
            const float* __restrict__ cbv,
            const float* __restrict__ rwb, const float* __restrict__ rrb,
            float* __restrict__ qw, float* __restrict__ qr,
            float* __restrict__ kh, float* __restrict__ vh)
{
    const int s  = blockIdx.z;
    const int hb = blockIdx.y;
    const int l0 = blockIdx.x * 128;
    const float* x  = convin + (long)(s * 64 + hb) * (64 * 1024);
    const float* wp = wpad + (long)s * (64 * 64 * 8);

    __shared__ float xs[64][136];
    for (int i = threadIdx.x; i < 64 * 134; i += 256) {
        int din = i / 134, c = i % 134;
        int gl = l0 - 3 + c;
        xs[din][c] = (gl >= 0 && gl < 1024) ? x[(long)din * 1024 + gl] : 0.f;
    }
    __syncthreads();

    const int lsub = threadIdx.x & 31;
    const int g    = threadIdx.x >> 5;

    float acc[8][4];
#pragma unroll
    for (int o = 0; o < 8; o++)
#pragma unroll
        for (int j = 0; j < 4; j++) acc[o][j] = 0.f;

    for (int din = 0; din < 64; din++) {
        float xv[4][7];
#pragma unroll
        for (int j = 0; j < 4; j++)
#pragma unroll
            for (int t = 0; t < 7; t++)
                xv[j][t] = xs[din][lsub + 32 * j + t];
#pragma unroll
        for (int o = 0; o < 8; o++) {
            const float4* wr = (const float4*)(wp + ((g * 8 + o) * 64 + din) * 8);
            float4 wa = __ldg(wr);
            float4 wb = __ldg(wr + 1);
            float wv[7] = {wa.x, wa.y, wa.z, wa.w, wb.x, wb.y, wb.z};
#pragma unroll
            for (int t = 0; t < 7; t++)
#pragma unroll
                for (int j = 0; j < 4; j++)
                    acc[o][j] += wv[t] * xv[j][t];
        }
    }

    const int h = hb >> 2;
#pragma unroll
    for (int o = 0; o < 8; o++) {
        int dout = g * 8 + o;
        long base = ((long)hb * 64 + dout) * 1024 + l0 + lsub;
        if (s == 0) {
            float bv = cbq[dout];
            float aw = rwb[h * 64 + dout];
            float ar = rrb[h * 64 + dout];
#pragma unroll
            for (int j = 0; j < 4; j++) {
                float v = acc[o][j] + bv;
                qw[base + 32 * j] = v + aw;
                qr[base + 32 * j] = v + ar;
            }
        } else if (s == 1) {
            float bv = cbk[dout];
#pragma unroll
            for (int j = 0; j < 4; j++) kh[base + 32 * j] = acc[o][j] + bv;
        } else {
            float bv = cbv[dout];
#pragma unroll
            for (int j = 0; j < 4; j++) vh[base + 32 * j] = acc[o][j] + bv;
        }
    }
}

// ---------------------------------------------------------------------------
// Fused rel-shift + causal mask + softmax (in-place into AC)
// ---------------------------------------------------------------------------
__global__ __launch_bounds__(256)
void softmax_k(float* __restrict__ acbuf, const float* __restrict__ bdbuf)
{
    const int i = blockIdx.x;
    const int z = blockIdx.y;
    float* ac       = acbuf + (long)z * (1024L * 1024) + (long)i * 1024;
    const float* bd = bdbuf + (long)z * (1024L * 1024) + (long)i * 1024 + (1023 - i);
    const int n = i + 1;
    __shared__ float red[8];
    const int tid = threadIdx.x;
    const int lane = tid & 31, wid = tid >> 5;

    float mx = -1e30f;
    for (int j = tid; j < n; j += 256)
        mx = fmaxf(mx, (ac[j] + bd[j]) * ATT_SCALE);
#pragma unroll
    for (int o = 16; o > 0; o >>= 1)
        mx = fmaxf(mx, __shfl_xor_sync(0xffffffffu, mx, o));
    if (lane == 0) red[wid] = mx;
    __syncthreads();
    if (tid == 0) {
        float m = red[0];
#pragma unroll
        for (int k = 1; k < 8; k++) m = fmaxf(m, red[k]);
        red[0] = m;
    }
    __syncthreads();
    const float MX = red[0];
    __syncthreads();

    float sum = 0.f;
    for (int j = tid; j < n; j += 256) {
        float e = __expf((ac[j] + bd[j]) * ATT_SCALE - MX);
        ac[j] = e;
        sum += e;
    }
#pragma unroll
    for (int o = 16; o > 0; o >>= 1)
        sum += __shfl_xor_sync(0xffffffffu, sum, o);
    if (lane == 0) red[wid] = sum;
    __syncthreads();
    if (tid == 0) {
        float sm = 0.f;
#pragma unroll
        for (int k = 0; k < 8; k++) sm += red[k];
        red[0] = 1.f / sm;
    }
    __syncthreads();
    const float inv = red[0];
    for (int j = tid; j < 1024; j += 256)
        ac[j] = (j < n) ? ac[j] * inv : 0.f;
}

// ---------------------------------------------------------------------------
// Fused residual + LayerNorm
// ---------------------------------------------------------------------------
__global__ __launch_bounds__(256)
void ln_k(const float* __restrict__ w, const float* __restrict__ attn,
          const float* __restrict__ gamma, const float* __restrict__ beta,
          float* __restrict__ out)
{
    const long t = blockIdx.x;
    __shared__ float xs[1024];
    __shared__ float red[8];
    const int tid = threadIdx.x, lane = tid & 31, wid = tid >> 5;

    float s = 0.f;
    for (int j = tid; j < 1024; j += 256) {
        float v = w[t * 1024 + j] + attn[t * 1024 + j];
        xs[j] = v;
        s += v;
    }
#pragma unroll
    for (int o = 16; o > 0; o >>= 1) s += __shfl_xor_sync(0xffffffffu, s, o);
    if (lane == 0) red[wid] = s;
    __syncthreads();
    if (tid == 0) {
        float tot = 0.f;
#pragma unroll
        for (int k = 0; k < 8; k++) tot += red[k];
        red[0] = tot * (1.f / 1024.f);
    }
    __syncthreads();
    const float mu = red[0];
    __syncthreads();

    float vs = 0.f;
    for (int j = tid; j < 1024; j += 256) {
        float d = xs[j] - mu;
        vs += d * d;
    }
#pragma unroll
    for (int o = 16; o > 0; o >>= 1) vs += __shfl_xor_sync(0xffffffffu, vs, o);
    if (lane == 0) red[wid] = vs;
    __syncthreads();
    if (tid == 0) {
        float tot = 0.f;
#pragma unroll
        for (int k = 0; k < 8; k++) tot += red[k];
        red[0] = rsqrtf(tot * (1.f / 1024.f) + 1e-5f);
    }
    __syncthreads();
    const float rstd = red[0];
    for (int j = tid; j < 1024; j += 256)
        out[t * 1024 + j] = (xs[j] - mu) * rstd * gamma[j] + beta[j];
}

// ---------------------------------------------------------------------------
// Orchestration
// ---------------------------------------------------------------------------
extern "C" void kernel_launch(void* const* d_in, const int* in_sizes, int n_in,
                              void* d_out, int out_size)
{
    (void)in_sizes; (void)n_in; (void)out_size;
    const float* w     = (const float*)d_in[0];
    const float* r     = (const float*)d_in[1];
    const float* rwb   = (const float*)d_in[2];
    const float* rrb   = (const float*)d_in[3];
    const float* Wqkv  = (const float*)d_in[4];
    const float* Wr    = (const float*)d_in[5];
    const float* Wo    = (const float*)d_in[6];
    const float* cwq   = (const float*)d_in[7];
    const float* cbq   = (const float*)d_in[8];
    const float* cwk   = (const float*)d_in[9];
    const float* cbk   = (const float*)d_in[10];
    const float* cwv   = (const float*)d_in[11];
    const float* cbv   = (const float*)d_in[12];
    const float* gamma = (const float*)d_in[13];
    const float* beta  = (const float*)d_in[14];
    float* out = (float*)d_out;

    float *heads, *convin, *rproj, *rhk, *qw, *qr, *kh, *vh, *ac, *bd, *vec, *attn, *wpad;
    __nv_bfloat16 *ahi, *alo, *bhi, *blo, *whi, *wlo;
    cudaGetSymbolAddress((void**)&heads,  g_heads);
    cudaGetSymbolAddress((void**)&convin, g_convin);
    cudaGetSymbolAddress((void**)&rproj,  g_rproj);
    cudaGetSymbolAddress((void**)&rhk,    g_rhk);
    cudaGetSymbolAddress((void**)&qw,     g_qw);
    cudaGetSymbolAddress((void**)&qr,     g_qr);
    cudaGetSymbolAddress((void**)&kh,     g_kh);
    cudaGetSymbolAddress((void**)&vh,     g_vh);
    cudaGetSymbolAddress((void**)&ac,     g_ac);
    cudaGetSymbolAddress((void**)&bd,     g_bd);
    cudaGetSymbolAddress((void**)&vec,    g_vec);
    cudaGetSymbolAddress((void**)&attn,   g_attn);
    cudaGetSymbolAddress((void**)&wpad,   g_wpad);
    cudaGetSymbolAddress((void**)&ahi,    g_ahi);
    cudaGetSymbolAddress((void**)&alo,    g_alo);
    cudaGetSymbolAddress((void**)&bhi,    g_bhi);
    cudaGetSymbolAddress((void**)&blo,    g_blo);
    cudaGetSymbolAddress((void**)&whi,    g_whi);
    cudaGetSymbolAddress((void**)&wlo,    g_wlo);

    const int MMA_SMEM = 2 * STGB;   // 81920 B
    cudaFuncSetAttribute(mma_gemm_k, cudaFuncAttributeMaxDynamicSharedMemorySize, MMA_SMEM);

    // 1. split-bf16 packs
    pack2_k<<<4096, 256>>>(w,    ahi, alo, 4096 * 256);
    pack2_k<<<3072, 256>>>(Wqkv, bhi, blo, 3072 * 256);
    pack2_k<<<1024, 256>>>(Wo,   whi, wlo, 1024 * 256);

    // 2. heads = w @ Wqkv^T   (mma.sync, split bf16)
    mma_gemm_k<<<dim3(24, 32), 256, MMA_SMEM>>>(ahi, alo, bhi, blo, heads, 3072, 1024);

    // 3. rproj = r @ Wr^T (SIMT, small)
    gemm_k<128,128,8,8,8,false,false,0,0><<<dim3(8, 8, 1), 256>>>(
        r, Wr, rproj, 1024, 1024, 1024, 1024, 0, 0, 0, 0);

    // 4. layout transposes
    transpose_heads_k<<<dim3(32, 96, 4), dim3(32, 8)>>>(heads, convin);
    transpose_r_k<<<dim3(32, 32), dim3(32, 8)>>>(rproj, rhk);

    // 5. conv weight padding + conv
    prep_w_k<<<(3 * 64 * 64 * 8 + 255) / 256, 256>>>(cwq, cwk, cwv, wpad);
    conv_k<<<dim3(8, 64, 3), 256>>>(convin, wpad, cbq, cbk, cbv, rwb, rrb,
                                    qw, qr, kh, vh);

    // 6. AC (causal skip)
    gemm_k<128,128,8,8,8,true,true,0,1><<<dim3(8, 8, 64), 256>>>(
        qw, kh, ac, 64, 1024, 1024, 1024, 65536L, 65536L, 0, 1048576L);

    // 7. BDraw (band skip)
    gemm_k<128,128,8,8,8,true,true,0,2><<<dim3(8, 8, 64), 256>>>(
        qr, rhk, bd, 64, 1024, 1024, 1024, 65536L, 65536L, 1, 1048576L);

    // 8. fused rel-shift + mask + softmax
    softmax_k<<<dim3(1024, 64), 256>>>(ac, bd);

    // 9. PV with causal K-bound
    gemm_k<128,64,8,8,4,false,false,1,3><<<dim3(1, 8, 64), 256>>>(
        ac, vh, vec, 1024, 1024, 1024, 4096, 1048576L, 65536L, 0, 0);

    // 10. attn = vec @ Wo^T (mma.sync, split bf16; reuse ahi/alo for vec)
    pack2_k<<<4096, 256>>>(vec, ahi, alo, 4096 * 256);
    mma_gemm_k<<<dim3(8, 32), 256, MMA_SMEM>>>(ahi, alo, whi, wlo, attn, 1024, 1024);

    // 11. out = LayerNorm(w + attn)
    ln_k<<<4096, 256>>>(w, attn, gamma, beta, out);
}

// round 13
// speedup vs baseline: 1.9557x; 1.2799x over previous
#include <cuda_runtime.h>
#include <cuda_bf16.h>
#include <cstdint>

// ---------------------------------------------------------------------------
// Problem constants
// ---------------------------------------------------------------------------
#define QLEN  1024
#define BSZ   4
#define NH    16
#define DH    64
#define DM    1024
#define NTOK  4096
#define NBH   64
#define ATT_SCALE 0.125f

// ---------------------------------------------------------------------------
// Device scratch
// ---------------------------------------------------------------------------
__device__ float g_heads [(long)NTOK * 3072];
__device__ float g_convin[(long)3 * NBH * DH * QLEN];
__device__ float g_rproj [(long)QLEN * DM];
__device__ float g_ac    [(long)NBH * QLEN * QLEN];   // fp32 AC scores
__device__ float g_bd    [(long)NBH * QLEN * QLEN];   // fp32 BD scores
__device__ float g_vec   [(long)NTOK * DM];
__device__ float g_attn  [(long)NTOK * DM];
__device__ float g_wpad  [3 * DH * DH * 8];

// Split-bf16 operands (hi/lo), 16B-aligned for cp.async
__device__ __align__(16) __nv_bfloat16 g_ahi[(long)4096 * 1024];
__device__ __align__(16) __nv_bfloat16 g_alo[(long)4096 * 1024];
__device__ __align__(16) __nv_bfloat16 g_bhi[(long)3072 * 1024];
__device__ __align__(16) __nv_bfloat16 g_blo[(long)3072 * 1024];
__device__ __align__(16) __nv_bfloat16 g_whi[(long)1024 * 1024];
__device__ __align__(16) __nv_bfloat16 g_wlo[(long)1024 * 1024];
// attention operands
__device__ __align__(16) __nv_bfloat16 g_qwh[(long)NBH * QLEN * DH];  // [z][l][d]
__device__ __align__(16) __nv_bfloat16 g_qwl[(long)NBH * QLEN * DH];
__device__ __align__(16) __nv_bfloat16 g_qrh[(long)NBH * QLEN * DH];
__device__ __align__(16) __nv_bfloat16 g_qrl[(long)NBH * QLEN * DH];
__device__ __align__(16) __nv_bfloat16 g_khh[(long)NBH * QLEN * DH];  // [z][l][d]
__device__ __align__(16) __nv_bfloat16 g_khl[(long)NBH * QLEN * DH];
__device__ __align__(16) __nv_bfloat16 g_vhh[(long)NBH * DH * QLEN];  // [z][d][l]
__device__ __align__(16) __nv_bfloat16 g_vhl[(long)NBH * DH * QLEN];
__device__ __align__(16) __nv_bfloat16 g_rph[(long)QLEN * DM];        // rproj hi
__device__ __align__(16) __nv_bfloat16 g_rpl[(long)QLEN * DM];
__device__ __align__(16) __nv_bfloat16 g_ph [(long)NBH * QLEN * QLEN]; // prob hi
__device__ __align__(16) __nv_bfloat16 g_pl [(long)NBH * QLEN * QLEN]; // prob lo

// ---------------------------------------------------------------------------
// Baseline-PTX helpers (plain sm_103 — no arch-suffix-gated features)
// ---------------------------------------------------------------------------
__device__ __forceinline__ uint32_t s2u(const void* p) {
    uint32_t a;
    asm("{ .reg .u64 t; cvta.to.shared.u64 t, %1; cvt.u32.u64 %0, t; }"
        : "=r"(a) : "l"(p));
    return a;
}
__device__ __forceinline__ void cpasync16(uint32_t dst, const void* src) {
    asm volatile("cp.async.cg.shared.global [%0], [%1], 16;" :: "r"(dst), "l"(src));
}
__device__ __forceinline__ void cp_commit() {
    asm volatile("cp.async.commit_group;" ::: "memory");
}
__device__ __forceinline__ void ldsm4(uint32_t* r, uint32_t a) {
    asm volatile("ldmatrix.sync.aligned.m8n8.x4.shared.b16 {%0,%1,%2,%3}, [%4];"
                 : "=r"(r[0]), "=r"(r[1]), "=r"(r[2]), "=r"(r[3]) : "r"(a));
}
__device__ __forceinline__ void mma16816(float* c, const uint32_t* a, const uint32_t* b) {
    asm volatile(
        "mma.sync.aligned.m16n8k16.row.col.f32.bf16.bf16.f32 "
        "{%0,%1,%2,%3}, {%4,%5,%6,%7}, {%8,%9}, {%0,%1,%2,%3};"
        : "+f"(c[0]), "+f"(c[1]), "+f"(c[2]), "+f"(c[3])
        : "r"(a[0]), "r"(a[1]), "r"(a[2]), "r"(a[3]), "r"(b[0]), "r"(b[1]));
}
__device__ __forceinline__ void splitpack(float a0, float a1, uint32_t& hw, uint32_t& lw) {
    __nv_bfloat16 h0 = __float2bfloat16(a0), h1 = __float2bfloat16(a1);
    __nv_bfloat16 l0 = __float2bfloat16(a0 - __bfloat162float(h0));
    __nv_bfloat16 l1 = __float2bfloat16(a1 - __bfloat162float(h1));
    hw = (uint32_t)*(unsigned short*)&h0 | ((uint32_t)*(unsigned short*)&h1 << 16);
    lw = (uint32_t)*(unsigned short*)&l0 | ((uint32_t)*(unsigned short*)&l1 << 16);
}

// ---------------------------------------------------------------------------
// Pack fp32 [rows][1024] -> hi/lo bf16 row-major
// ---------------------------------------------------------------------------
__global__ __launch_bounds__(256)
void pack2_k(const float* __restrict__ X, __nv_bfloat16* __restrict__ Hi,
             __nv_bfloat16* __restrict__ Lo, int n4)
{
    int i = blockIdx.x * 256 + threadIdx.x;
    if (i >= n4) return;
    float4 v = ((const float4*)X)[i];
    uint32_t h0, l0, h1, l1;
    splitpack(v.x, v.y, h0, l0);
    splitpack(v.z, v.w, h1, l1);
    *(uint2*)(Hi + 4L * i) = make_uint2(h0, h1);
    *(uint2*)(Lo + 4L * i) = make_uint2(l0, l1);
}

// ---------------------------------------------------------------------------
// Batched tensor-core GEMM via mma.sync, split-bf16 3-MMA compensation.
// C[m][n] = sum_k A[m][k]*B[n][k].   A: [M][K] row-major (lda), B: [N][K] (ldb).
// BM=128, BK=32, 8 warps (4x2), warp tile 32 x (BN/2).
// MASK 0: none ; 1: AC causal block skip ; 2: BD band skip ; 3: PV K-bound.
// CMODE 0: C + z*cStride ; 1: PV scatter (z&3)*1024 + (z>>2)*64.
// ---------------------------------------------------------------------------
template<int BN, int CMODE, int MASK>
__global__ __launch_bounds__(256, 2)
void mma_batch_k(const __nv_bfloat16* __restrict__ Ah, const __nv_bfloat16* __restrict__ Al,
                 const __nv_bfloat16* __restrict__ Bh, const __nv_bfloat16* __restrict__ Bl,
                 float* __restrict__ C, int lda, int ldb, int ldc, int K,
                 long aStride, long bStride, int bShift, long cStride)
{
    constexpr int MATA  = 128 * 40 * 2;    // A tile bytes (hi or lo), 40-half padded rows
    constexpr int MATB2 = BN * 40 * 2;
    constexpr int STG   = 2 * MATA + 2 * MATB2;
    constexpr int NP    = BN / 32;         // B fragment groups per warp
    constexpr int NT8   = BN / 16;         // acc n-tiles per warp

    extern __shared__ __align__(16) unsigned char sm_raw[];
    const uint32_t sb = s2u(sm_raw);
    const int tid = threadIdx.x, lane = tid & 31, wid = tid >> 5;
    const int m0 = blockIdx.y * 128, n0 = blockIdx.x * BN;
    const int z  = blockIdx.z;
    const int wm = wid & 3, wn = wid >> 2;

    if (MASK == 1 && n0 > m0 + 127) return;
    if (MASK == 2 && m0 + n0 + 128 + BN <= 1024) return;
    if (MASK == 3) K = (K < m0 + 128) ? K : (m0 + 128);

    const __nv_bfloat16* A_h = Ah + (long)z * aStride;
    const __nv_bfloat16* A_l = Al + (long)z * aStride;
    const long boff = bShift ? (long)(z >> 2) * bStride : (long)z * bStride;
    const __nv_bfloat16* B_h = Bh + boff;
    const __nv_bfloat16* B_l = Bl + boff;
    float* Cb;
    if (CMODE == 0) Cb = C + (long)z * cStride;
    else            Cb = C + (long)(z & 3) * 1024 + (long)(z >> 2) * 64;

    const int lr = tid >> 2;     // loader row base (0..63)
    const int lc = tid & 3;      // loader 16B chunk (0..3)

    float acc[2][NT8][4];
#pragma unroll
    for (int a = 0; a < 2; a++)
#pragma unroll
        for (int b = 0; b < NT8; b++)
#pragma unroll
            for (int d = 0; d < 4; d++) acc[a][b][d] = 0.f;

#define STAGE_LOAD(T, BUF)                                                    \
    {                                                                         \
        uint32_t s0 = sb + (BUF) * STG;                                       \
        int k0 = (T) * 32;                                                    \
        _Pragma("unroll")                                                     \
        for (int it = 0; it < 2; it++) {                                      \
            int row = lr + it * 64;                                           \
            uint32_t so = (uint32_t)(row * 40 + lc * 8) * 2;                  \
            long ga = (long)(m0 + row) * lda + k0 + lc * 8;                   \
            cpasync16(s0 + so,        A_h + ga);                              \
            cpasync16(s0 + MATA + so, A_l + ga);                              \
        }                                                                     \
        _Pragma("unroll")                                                     \
        for (int it = 0; it < BN / 64; it++) {                                \
            int row = lr + it * 64;                                           \
            uint32_t so = (uint32_t)(row * 40 + lc * 8) * 2;                  \
            long gb = (long)(n0 + row) * ldb + k0 + lc * 8;                   \
            cpasync16(s0 + 2 * MATA + so,         B_h + gb);                  \
            cpasync16(s0 + 2 * MATA + MATB2 + so, B_l + gb);                  \
        }                                                                     \
    }

    STAGE_LOAD(0, 0)
    cp_commit();

    const int T = K / 32;
    for (int t = 0; t < T; t++) {
        const int cur = t & 1;
        if (t + 1 < T) {
            STAGE_LOAD(t + 1, cur ^ 1)
            cp_commit();
            asm volatile("cp.async.wait_group 1;" ::: "memory");
        } else {
            asm volatile("cp.async.wait_group 0;" ::: "memory");
        }
        __syncthreads();

        const uint32_t s0 = sb + cur * STG;
#pragma unroll
        for (int ks = 0; ks < 2; ks++) {
            const int k0 = ks * 16;
            uint32_t ah[2][4], al[2][4], bh[NP][4], bl[NP][4];
#pragma unroll
            for (int mt = 0; mt < 2; mt++) {
                int row = wm * 32 + mt * 16 + (lane & 15);
                int col = k0 + ((lane >> 4) << 3);
                uint32_t ao = (uint32_t)(row * 40 + col) * 2;
                ldsm4(ah[mt], s0 + ao);
                ldsm4(al[mt], s0 + MATA + ao);
            }
#pragma unroll
            for (int p = 0; p < NP; p++) {
                int row = wn * (BN / 2) + p * 16 + ((lane >> 4) << 3) + (lane & 7);
                int col = k0 + (((lane >> 3) & 1) << 3);
                uint32_t bo = (uint32_t)(row * 40 + col) * 2;
                ldsm4(bh[p], s0 + 2 * MATA + bo);
                ldsm4(bl[p], s0 + 2 * MATA + MATB2 + bo);
            }
#pragma unroll
            for (int mt = 0; mt < 2; mt++)
#pragma unroll
                for (int nt = 0; nt < NT8; nt++)
                    mma16816(acc[mt][nt], ah[mt], &bh[nt >> 1][(nt & 1) * 2]);
#pragma unroll
            for (int mt = 0; mt < 2; mt++)
#pragma unroll
                for (int nt = 0; nt < NT8; nt++)
                    mma16816(acc[mt][nt], ah[mt], &bl[nt >> 1][(nt & 1) * 2]);
#pragma unroll
            for (int mt = 0; mt < 2; mt++)
#pragma unroll
                for (int nt = 0; nt < NT8; nt++)
                    mma16816(acc[mt][nt], al[mt], &bh[nt >> 1][(nt & 1) * 2]);
        }
        __syncthreads();
    }

#pragma unroll
    for (int mt = 0; mt < 2; mt++) {
        int row = m0 + wm * 32 + mt * 16 + (lane >> 2);
#pragma unroll
        for (int nt = 0; nt < NT8; nt++) {
            int col = n0 + wn * (BN / 2) + nt * 8 + (lane & 3) * 2;
            *(float2*)(Cb + (long)row * ldc + col) =
                make_float2(acc[mt][nt][0], acc[mt][nt][1]);
            *(float2*)(Cb + (long)(row + 8) * ldc + col) =
                make_float2(acc[mt][nt][2], acc[mt][nt][3]);
        }
    }
#undef STAGE_LOAD
}

// ---------------------------------------------------------------------------
// SIMT double-buffered SGEMM (only for the tiny rproj GEMM)
// ---------------------------------------------------------------------------
template<int BM,int BN,int BK,int TM,int TN>
__global__ __launch_bounds__((BM/TM)*(BN/TN))
void gemm_k(const float* __restrict__ A, const float* __restrict__ B,
            float* __restrict__ C, int K, int lda, int ldb, int ldc)
{
    constexpr int TX = BN / TN;
    constexpr int TY = BM / TM;
    constexpr int NT = TX * TY;
    constexpr int NA = BM * BK / 4;
    constexpr int NB = BN * BK / 4;
    constexpr int LA = (NA + NT - 1) / NT;
    constexpr int LB = (NB + NT - 1) / NT;

    const int tid = threadIdx.x;
    const int m0  = blockIdx.y * BM;
    const int n0  = blockIdx.x * BN;

    __shared__ float As[2][BK][BM + 4];
    __shared__ float Bs[2][BK][BN + 4];

    const int tx = tid % TX;
    const int ty = tid / TX;

    float acc[TM][TN];
#pragma unroll
    for (int i = 0; i < TM; i++)
#pragma unroll
        for (int j = 0; j < TN; j++) acc[i][j] = 0.f;

    float4 ra[LA], rb[LB];

#define LOAD_AB(K0)                                                            \
    _Pragma("unroll")                                                          \
    for (int u = 0; u < LA; u++) {                                             \
        int i = tid + u * NT;                                                  \
        int r = i / (BK/4), q = i % (BK/4);                                    \
        ra[u] = *(const float4*)(A + (long)(m0 + r) * lda + (K0) + q*4);       \
    }                                                                          \
    _Pragma("unroll")                                                          \
    for (int u = 0; u < LB; u++) {                                             \
        int i = tid + u * NT;                                                  \
        int r = i / (BK/4), q = i % (BK/4);                                    \
        rb[u] = *(const float4*)(B + (long)(n0 + r) * ldb + (K0) + q*4);       \
    }
#define STORE_AB(BUF)                                                          \
    _Pragma("unroll")                                                          \
    for (int u = 0; u < LA; u++) {                                             \
        int i = tid + u * NT;                                                  \
        int r = i / (BK/4), q = i % (BK/4);                                    \
        As[BUF][q*4+0][r] = ra[u].x; As[BUF][q*4+1][r] = ra[u].y;              \
        As[BUF][q*4+2][r] = ra[u].z; As[BUF][q*4+3][r] = ra[u].w;              \
    }                                                                          \
    _Pragma("unroll")                                                          \
    for (int u = 0; u < LB; u++) {                                             \
        int i = tid + u * NT;                                                  \
        int r = i / (BK/4), q = i % (BK/4);                                    \
        Bs[BUF][q*4+0][r] = rb[u].x; Bs[BUF][q*4+1][r] = rb[u].y;              \
        Bs[BUF][q*4+2][r] = rb[u].z; Bs[BUF][q*4+3][r] = rb[u].w;              \
    }

    LOAD_AB(0)
    STORE_AB(0)
    __syncthreads();

    const int ktiles = K / BK;
    for (int t = 0; t < ktiles; t++) {
        const int cur = t & 1;
        if (t + 1 < ktiles) { LOAD_AB((t + 1) * BK) }
#pragma unroll
        for (int kk = 0; kk < BK; kk++) {
            float a[TM], b[TN];
#pragma unroll
            for (int u = 0; u < TM / 4; u++)
                *(float4*)&a[u * 4] = *(const float4*)&As[cur][kk][ty * TM + u * 4];
#pragma unroll
            for (int u = 0; u < TN / 4; u++)
                *(float4*)&b[u * 4] = *(const float4*)&Bs[cur][kk][tx * TN + u * 4];
#pragma unroll
            for (int i = 0; i < TM; i++)
#pragma unroll
                for (int j = 0; j < TN; j++)
                    acc[i][j] += a[i] * b[j];
        }
        if (t + 1 < ktiles) {
            STORE_AB(cur ^ 1)
            __syncthreads();
        }
    }

#pragma unroll
    for (int i = 0; i < TM; i++) {
        long row = m0 + ty * TM + i;
#pragma unroll
        for (int u = 0; u < TN / 4; u++) {
            float4 v = make_float4(acc[i][u*4+0], acc[i][u*4+1],
                                   acc[i][u*4+2], acc[i][u*4+3]);
            *(float4*)(C + row * ldc + n0 + tx * TN + u * 4) = v;
        }
    }
#undef LOAD_AB
#undef STORE_AB
}

// ---------------------------------------------------------------------------
// Transpose heads -> conv input layout
// ---------------------------------------------------------------------------
__global__ void transpose_heads_k(const float* __restrict__ heads,
                                  float* __restrict__ convin)
{
    __shared__ float tile[32][33];
    const int q0 = blockIdx.x * 32;
    const int c0 = blockIdx.y * 32;
    const int b  = blockIdx.z;
    const int x = threadIdx.x, y = threadIdx.y;
#pragma unroll
    for (int yy = 0; yy < 32; yy += 8)
        tile[yy + y][x] = heads[((long)(q0 + yy + y) * 4 + b) * 3072 + c0 + x];
    __syncthreads();
#pragma unroll
    for (int yy = 0; yy < 32; yy += 8) {
        int ch = c0 + yy + y;
        int s = ch >> 10, rem = ch & 1023, h = rem >> 6, d = rem & 63;
        convin[((long)(s * 64 + h * 4 + b) * 64 + d) * 1024 + q0 + x] = tile[x][yy + y];
    }
}

__global__ void prep_w_k(const float* __restrict__ wq, const float* __restrict__ wk,
                         const float* __restrict__ wv, float* __restrict__ wpad)
{
    int i = blockIdx.x * 256 + threadIdx.x;
    if (i >= 3 * 64 * 64 * 8) return;
    int t  = i & 7;
    int oi = (i >> 3) & 4095;
    int s  = i >> 15;
    const float* src = (s == 0) ? wq : (s == 1) ? wk : wv;
    wpad[i] = (t < 7) ? src[oi * 7 + t] : 0.f;
}

// ---------------------------------------------------------------------------
// Conv1d + fused bias, emits split-bf16 MMA operands directly:
//   s=0: qw/qr hi+lo in [z][l][d] (smem-staged, coalesced)
//   s=1: kh    hi+lo in [z][l][d]
//   s=2: vh    hi+lo in [z][d][l] (direct, already coalesced)
// ---------------------------------------------------------------------------
__global__ __launch_bounds__(256)
void conv_k(const float* __restrict__ convin, const float* __restrict__ wpad,
            const float* __restrict__ cbq, const float* __restrict__ cbk,
            const float* __restrict__ cbv,
            const float* __restrict__ rwb, const float* __restrict__ rrb,
            __nv_bfloat16* __restrict__ qwh, __nv_bfloat16* __restrict__ qwl,
            __nv_bfloat16* __restrict__ qrh, __nv_bfloat16* __restrict__ qrl,
            __nv_bfloat16* __restrict__ khh, __nv_bfloat16* __restrict__ khl,
            __nv_bfloat16* __restrict__ vhh, __nv_bfloat16* __restrict__ vhl)
{
    const int s  = blockIdx.z;
    const int hb = blockIdx.y;
    const int l0 = blockIdx.x * 128;
    const float* x  = convin + (long)(s * 64 + hb) * (64 * 1024);
    const float* wp = wpad + (long)s * (64 * 64 * 8);

    __shared__ float xs[64][136];
    for (int i = threadIdx.x; i < 64 * 134; i += 256) {
        int din = i / 134, c = i % 134;
        int gl = l0 - 3 + c;
        xs[din][c] = (gl >= 0 && gl < 1024) ? x[(long)din * 1024 + gl] : 0.f;
    }
    __syncthreads();

    const int lsub = threadIdx.x & 31;
    const int g    = threadIdx.x >> 5;

    float acc[8][4];
#pragma unroll
    for (int o = 0; o < 8; o++)
#pragma unroll
        for (int j = 0; j < 4; j++) acc[o][j] = 0.f;

    for (int din = 0; din < 64; din++) {
        float xv[4][7];
#pragma unroll
        for (int j = 0; j < 4; j++)
#pragma unroll
            for (int t = 0; t < 7; t++)
                xv[j][t] = xs[din][lsub + 32 * j + t];
#pragma unroll
        for (int o = 0; o < 8; o++) {
            const float4* wr = (const float4*)(wp + ((g * 8 + o) * 64 + din) * 8);
            float4 wa = __ldg(wr);
            float4 wb = __ldg(wr + 1);
            float wv[7] = {wa.x, wa.y, wa.z, wa.w, wb.x, wb.y, wb.z};
#pragma unroll
            for (int t = 0; t < 7; t++)
#pragma unroll
                for (int j = 0; j < 4; j++)
                    acc[o][j] += wv[t] * xv[j][t];
        }
    }

    if (s == 2) {
        // v: [z][d][l] hi/lo, consecutive lsub -> consecutive addresses
#pragma unroll
        for (int o = 0; o < 8; o++) {
            int dout = g * 8 + o;
            float bv = cbv[dout];
            long base = ((long)hb * 64 + dout) * 1024 + l0 + lsub;
#pragma unroll
            for (int j = 0; j < 4; j++) {
                float v = acc[o][j] + bv;
                __nv_bfloat16 h = __float2bfloat16(v);
                __nv_bfloat16 l = __float2bfloat16(v - __bfloat162float(h));
                vhh[base + 32 * j] = h;
                vhl[base + 32 * j] = l;
            }
        }
        return;
    }

    // stage (acc + conv bias) into smem [l 128][d 64] (65-pad), then write [z][l][d]
    __syncthreads();                       // all xs reads complete before overlay
    float* stg = (float*)xs;               // 128*65 = 8320 <= 8704 floats
#pragma unroll
    for (int o = 0; o < 8; o++) {
        int dout = g * 8 + o;
        float cb = (s == 0) ? cbq[dout] : cbk[dout];
#pragma unroll
        for (int j = 0; j < 4; j++)
            stg[(lsub + 32 * j) * 65 + dout] = acc[o][j] + cb;
    }
    __syncthreads();

    const int h   = hb >> 2;
    const int row = threadIdx.x >> 1;
    const int d0  = (threadIdx.x & 1) * 32;
    const long ob = ((long)hb * 1024 + l0 + row) * 64 + d0;

    if (s == 0) {
#pragma unroll
        for (int dd = 0; dd < 32; dd += 2) {
            float v0 = stg[row * 65 + d0 + dd];
            float v1 = stg[row * 65 + d0 + dd + 1];
            float b0 = rwb[h * 64 + d0 + dd], b1 = rwb[h * 64 + d0 + dd + 1];
            float c0 = rrb[h * 64 + d0 + dd], c1 = rrb[h * 64 + d0 + dd + 1];
            uint32_t hw, lw;
            splitpack(v0 + b0, v1 + b1, hw, lw);
            *(uint32_t*)(qwh + ob + dd) = hw;
            *(uint32_t*)(qwl + ob + dd) = lw;
            splitpack(v0 + c0, v1 + c1, hw, lw);
            *(uint32_t*)(qrh + ob + dd) = hw;
            *(uint32_t*)(qrl + ob + dd) = lw;
        }
    } else {
#pragma unroll
        for (int dd = 0; dd < 32; dd += 2) {
            float v0 = stg[row * 65 + d0 + dd];
            float v1 = stg[row * 65 + d0 + dd + 1];
            uint32_t hw, lw;
            splitpack(v0, v1, hw, lw);
            *(uint32_t*)(khh + ob + dd) = hw;
            *(uint32_t*)(khl + ob + dd) = lw;
        }
    }
}

// ---------------------------------------------------------------------------
// Fused rel-shift + causal mask + softmax; emits prob as split-bf16 (PV's A).
// Uses ac as fp32 scratch for the exp pass.
// ---------------------------------------------------------------------------
__global__ __launch_bounds__(256)
void softmax_k(float* __restrict__ acbuf, const float* __restrict__ bdbuf,
               __nv_bfloat16* __restrict__ ph, __nv_bfloat16* __restrict__ pl)
{
    const int i = blockIdx.x;
    const int z = blockIdx.y;
    float* ac       = acbuf + (long)z * (1024L * 1024) + (long)i * 1024;
    const float* bd = bdbuf + (long)z * (1024L * 1024) + (long)i * 1024 + (1023 - i);
    const int n = i + 1;
    __shared__ float red[8];
    const int tid = threadIdx.x;
    const int lane = tid & 31, wid = tid >> 5;

    float mx = -1e30f;
    for (int j = tid; j < n; j += 256)
        mx = fmaxf(mx, (ac[j] + bd[j]) * ATT_SCALE);
#pragma unroll
    for (int o = 16; o > 0; o >>= 1)
        mx = fmaxf(mx, __shfl_xor_sync(0xffffffffu, mx, o));
    if (lane == 0) red[wid] = mx;
    __syncthreads();
    if (tid == 0) {
        float m = red[0];
#pragma unroll
        for (int k = 1; k < 8; k++) m = fmaxf(m, red[k]);
        red[0] = m;
    }
    __syncthreads();
    const float MX = red[0];
    __syncthreads();

    float sum = 0.f;
    for (int j = tid; j < n; j += 256) {
        float e = __expf((ac[j] + bd[j]) * ATT_SCALE - MX);
        ac[j] = e;
        sum += e;
    }
#pragma unroll
    for (int o = 16; o > 0; o >>= 1)
        sum += __shfl_xor_sync(0xffffffffu, sum, o);
    if (lane == 0) red[wid] = sum;
    __syncthreads();
    if (tid == 0) {
        float sm = 0.f;
#pragma unroll
        for (int k = 0; k < 8; k++) sm += red[k];
        red[0] = 1.f / sm;
    }
    __syncthreads();
    const float inv = red[0];

    // each thread writes 4 consecutive j as packed uint2 (hi) + uint2 (lo)
    const int j0 = tid * 4;
    float p0 = (j0 + 0 < n) ? ac[j0 + 0] * inv : 0.f;
    float p1 = (j0 + 1 < n) ? ac[j0 + 1] * inv : 0.f;
    float p2 = (j0 + 2 < n) ? ac[j0 + 2] * inv : 0.f;
    float p3 = (j0 + 3 < n) ? ac[j0 + 3] * inv : 0.f;
    uint32_t h0, l0, h1, l1;
    splitpack(p0, p1, h0, l0);
    splitpack(p2, p3, h1, l1);
    long idx = (long)z * (1024L * 1024) + (long)i * 1024 + j0;
    *(uint2*)(ph + idx) = make_uint2(h0, h1);
    *(uint2*)(pl + idx) = make_uint2(l0, l1);
}

// ---------------------------------------------------------------------------
// Fused residual + LayerNorm
// ---------------------------------------------------------------------------
__global__ __launch_bounds__(256)
void ln_k(const float* __restrict__ w, const float* __restrict__ attn,
          const float* __restrict__ gamma, const float* __restrict__ beta,
          float* __restrict__ out)
{
    const long t = blockIdx.x;
    __shared__ float xs[1024];
    __shared__ float red[8];
    const int tid = threadIdx.x, lane = tid & 31, wid = tid >> 5;

    float s = 0.f;
    for (int j = tid; j < 1024; j += 256) {
        float v = w[t * 1024 + j] + attn[t * 1024 + j];
        xs[j] = v;
        s += v;
    }
#pragma unroll
    for (int o = 16; o > 0; o >>= 1) s += __shfl_xor_sync(0xffffffffu, s, o);
    if (lane == 0) red[wid] = s;
    __syncthreads();
    if (tid == 0) {
        float tot = 0.f;
#pragma unroll
        for (int k = 0; k < 8; k++) tot += red[k];
        red[0] = tot * (1.f / 1024.f);
    }
    __syncthreads();
    const float mu = red[0];
    __syncthreads();

    float vs = 0.f;
    for (int j = tid; j < 1024; j += 256) {
        float d = xs[j] - mu;
        vs += d * d;
    }
#pragma unroll
    for (int o = 16; o > 0; o >>= 1) vs += __shfl_xor_sync(0xffffffffu, vs, o);
    if (lane == 0) red[wid] = vs;
    __syncthreads();
    if (tid == 0) {
        float tot = 0.f;
#pragma unroll
        for (int k = 0; k < 8; k++) tot += red[k];
        red[0] = rsqrtf(tot * (1.f / 1024.f) + 1e-5f);
    }
    __syncthreads();
    const float rstd = red[0];
    for (int j = tid; j < 1024; j += 256)
        out[t * 1024 + j] = (xs[j] - mu) * rstd * gamma[j] + beta[j];
}

// ---------------------------------------------------------------------------
// Orchestration
// ---------------------------------------------------------------------------
extern "C" void kernel_launch(void* const* d_in, const int* in_sizes, int n_in,
                              void* d_out, int out_size)
{
    (void)in_sizes; (void)n_in; (void)out_size;
    const float* w     = (const float*)d_in[0];
    const float* r     = (const float*)d_in[1];
    const float* rwb   = (const float*)d_in[2];
    const float* rrb   = (const float*)d_in[3];
    const float* Wqkv  = (const float*)d_in[4];
    const float* Wr    = (const float*)d_in[5];
    const float* Wo    = (const float*)d_in[6];
    const float* cwq   = (const float*)d_in[7];
    const float* cbq   = (const float*)d_in[8];
    const float* cwk   = (const float*)d_in[9];
    const float* cbk   = (const float*)d_in[10];
    const float* cwv   = (const float*)d_in[11];
    const float* cbv   = (const float*)d_in[12];
    const float* gamma = (const float*)d_in[13];
    const float* beta  = (const float*)d_in[14];
    float* out = (float*)d_out;

    float *heads, *convin, *rproj, *ac, *bd, *vec, *attn, *wpad;
    __nv_bfloat16 *ahi, *alo, *bhi, *blo, *whi, *wlo;
    __nv_bfloat16 *qwh, *qwl, *qrh, *qrl, *khh, *khl, *vhh, *vhl, *rph, *rpl, *ph, *pl;
    cudaGetSymbolAddress((void**)&heads,  g_heads);
    cudaGetSymbolAddress((void**)&convin, g_convin);
    cudaGetSymbolAddress((void**)&rproj,  g_rproj);
    cudaGetSymbolAddress((void**)&ac,     g_ac);
    cudaGetSymbolAddress((void**)&bd,     g_bd);
    cudaGetSymbolAddress((void**)&vec,    g_vec);
    cudaGetSymbolAddress((void**)&attn,   g_attn);
    cudaGetSymbolAddress((void**)&wpad,   g_wpad);
    cudaGetSymbolAddress((void**)&ahi,    g_ahi);
    cudaGetSymbolAddress((void**)&alo,    g_alo);
    cudaGetSymbolAddress((void**)&bhi,    g_bhi);
    cudaGetSymbolAddress((void**)&blo,    g_blo);
    cudaGetSymbolAddress((void**)&whi,    g_whi);
    cudaGetSymbolAddress((void**)&wlo,    g_wlo);
    cudaGetSymbolAddress((void**)&qwh,    g_qwh);
    cudaGetSymbolAddress((void**)&qwl,    g_qwl);
    cudaGetSymbolAddress((void**)&qrh,    g_qrh);
    cudaGetSymbolAddress((void**)&qrl,    g_qrl);
    cudaGetSymbolAddress((void**)&khh,    g_khh);
    cudaGetSymbolAddress((void**)&khl,    g_khl);
    cudaGetSymbolAddress((void**)&vhh,    g_vhh);
    cudaGetSymbolAddress((void**)&vhl,    g_vhl);
    cudaGetSymbolAddress((void**)&rph,    g_rph);
    cudaGetSymbolAddress((void**)&rpl,    g_rpl);
    cudaGetSymbolAddress((void**)&ph,     g_ph);
    cudaGetSymbolAddress((void**)&pl,     g_pl);

    const int SM128 = 2 * (2 * 128 * 40 * 2 + 2 * 128 * 40 * 2);  // 81920
    const int SM64  = 2 * (2 * 128 * 40 * 2 + 2 *  64 * 40 * 2);  // 61440
    cudaFuncSetAttribute(mma_batch_k<128,0,0>, cudaFuncAttributeMaxDynamicSharedMemorySize, SM128);
    cudaFuncSetAttribute(mma_batch_k<128,0,1>, cudaFuncAttributeMaxDynamicSharedMemorySize, SM128);
    cudaFuncSetAttribute(mma_batch_k<128,0,2>, cudaFuncAttributeMaxDynamicSharedMemorySize, SM128);
    cudaFuncSetAttribute(mma_batch_k<64,1,3>,  cudaFuncAttributeMaxDynamicSharedMemorySize, SM64);

    // 1. split-bf16 packs for QKV / Wo
    pack2_k<<<4096, 256>>>(w,    ahi, alo, 4096 * 256);
    pack2_k<<<3072, 256>>>(Wqkv, bhi, blo, 3072 * 256);
    pack2_k<<<1024, 256>>>(Wo,   whi, wlo, 1024 * 256);

    // 2. heads = w @ Wqkv^T (HMMA)
    mma_batch_k<128,0,0><<<dim3(24, 32, 1), 256, SM128>>>(
        ahi, alo, bhi, blo, heads, 1024, 1024, 3072, 1024, 0, 0, 0, 0);

    // 3. rproj = r @ Wr^T (SIMT, small), then pack hi/lo for BD's B operand
    gemm_k<128,128,8,8,8><<<dim3(8, 8, 1), 256>>>(r, Wr, rproj, 1024, 1024, 1024, 1024);
    pack2_k<<<1024, 256>>>(rproj, rph, rpl, 1024 * 256);

    // 4. conv input transpose + conv (emits split-bf16 attention operands)
    transpose_heads_k<<<dim3(32, 96, 4), dim3(32, 8)>>>(heads, convin);
    prep_w_k<<<(3 * 64 * 64 * 8 + 255) / 256, 256>>>(cwq, cwk, cwv, wpad);
    conv_k<<<dim3(8, 64, 3), 256>>>(convin, wpad, cbq, cbk, cbv, rwb, rrb,
                                    qwh, qwl, qrh, qrl, khh, khl, vhh, vhl);

    // 5. AC scores (HMMA, causal block skip)
    mma_batch_k<128,0,1><<<dim3(8, 8, 64), 256, SM128>>>(
        qwh, qwl, khh, khl, ac, 64, 64, 1024, 64, 65536L, 65536L, 0, 1048576L);

    // 6. BD scores (HMMA, band skip; B = per-head slice of packed rproj)
    mma_batch_k<128,0,2><<<dim3(8, 8, 64), 256, SM128>>>(
        qrh, qrl, rph, rpl, bd, 64, 1024, 1024, 64, 65536L, 64L, 1, 1048576L);

    // 7. fused rel-shift + mask + softmax -> prob hi/lo
    softmax_k<<<dim3(1024, 64), 256>>>(ac, bd, ph, pl);

    // 8. PV (HMMA, K-bounded by causality, scatter epilogue)
    mma_batch_k<64,1,3><<<dim3(1, 8, 64), 256, SM64>>>(
        ph, pl, vhh, vhl, vec, 1024, 1024, 4096, 1024, 1048576L, 65536L, 0, 0);

    // 9. attn = vec @ Wo^T (HMMA; reuse ahi/alo for packed vec)
    pack2_k<<<4096, 256>>>(vec, ahi, alo, 4096 * 256);
    mma_batch_k<128,0,0><<<dim3(8, 32, 1), 256, SM128>>>(
        ahi, alo, whi, wlo, attn, 1024, 1024, 1024, 1024, 0, 0, 0, 0);

    // 10. out = LayerNorm(w + attn)
    ln_k<<<4096, 256>>>(w, attn, gamma, beta, out);
}

// round 14
// speedup vs baseline: 2.3025x; 1.1773x over previous
#include <cuda_runtime.h>
#include <cuda_bf16.h>
#include <cstdint>

// ---------------------------------------------------------------------------
// Problem constants
// ---------------------------------------------------------------------------
#define QLEN  1024
#define BSZ   4
#define NH    16
#define DH    64
#define DM    1024
#define NTOK  4096
#define NBH   64

// ---------------------------------------------------------------------------
// Device scratch
// ---------------------------------------------------------------------------
__device__ float g_heads [(long)NTOK * 3072];
__device__ float g_rproj [(long)QLEN * DM];
__device__ float g_ac    [(long)NBH * QLEN * QLEN];   // fused scaled scores
__device__ float g_bd    [(long)NBH * QLEN * QLEN];   // raw BD
__device__ float g_vec   [(long)NTOK * DM];
__device__ float g_attn  [(long)NTOK * DM];

// Split-bf16 operands
__device__ __align__(16) __nv_bfloat16 g_ahi[(long)4096 * 1024];
__device__ __align__(16) __nv_bfloat16 g_alo[(long)4096 * 1024];
__device__ __align__(16) __nv_bfloat16 g_bhi[(long)3072 * 1024];
__device__ __align__(16) __nv_bfloat16 g_blo[(long)3072 * 1024];
__device__ __align__(16) __nv_bfloat16 g_whi[(long)1024 * 1024];
__device__ __align__(16) __nv_bfloat16 g_wlo[(long)1024 * 1024];
// conv weights packed [s][dout][t*64+din], hi/lo
__device__ __align__(16) __nv_bfloat16 g_cwh[3 * 64 * 448];
__device__ __align__(16) __nv_bfloat16 g_cwl[3 * 64 * 448];
// attention operands
__device__ __align__(16) __nv_bfloat16 g_qwh[(long)NBH * QLEN * DH];  // [z][l][d]
__device__ __align__(16) __nv_bfloat16 g_qwl[(long)NBH * QLEN * DH];
__device__ __align__(16) __nv_bfloat16 g_qrh[(long)NBH * QLEN * DH];
__device__ __align__(16) __nv_bfloat16 g_qrl[(long)NBH * QLEN * DH];
__device__ __align__(16) __nv_bfloat16 g_khh[(long)NBH * QLEN * DH];
__device__ __align__(16) __nv_bfloat16 g_khl[(long)NBH * QLEN * DH];
__device__ __align__(16) __nv_bfloat16 g_vhh[(long)NBH * DH * QLEN];  // [z][d][l]
__device__ __align__(16) __nv_bfloat16 g_vhl[(long)NBH * DH * QLEN];
__device__ __align__(16) __nv_bfloat16 g_rph[(long)QLEN * DM];
__device__ __align__(16) __nv_bfloat16 g_rpl[(long)QLEN * DM];
__device__ __align__(16) __nv_bfloat16 g_ph [(long)NBH * QLEN * QLEN];
__device__ __align__(16) __nv_bfloat16 g_pl [(long)NBH * QLEN * QLEN];

// ---------------------------------------------------------------------------
// Baseline-PTX helpers (plain sm_103)
// ---------------------------------------------------------------------------
__device__ __forceinline__ uint32_t s2u(const void* p) {
    uint32_t a;
    asm("{ .reg .u64 t; cvta.to.shared.u64 t, %1; cvt.u32.u64 %0, t; }"
        : "=r"(a) : "l"(p));
    return a;
}
__device__ __forceinline__ void cpasync16(uint32_t dst, const void* src) {
    asm volatile("cp.async.cg.shared.global [%0], [%1], 16;" :: "r"(dst), "l"(src));
}
__device__ __forceinline__ void cp_commit() {
    asm volatile("cp.async.commit_group;" ::: "memory");
}
__device__ __forceinline__ void ldsm4(uint32_t* r, uint32_t a) {
    asm volatile("ldmatrix.sync.aligned.m8n8.x4.shared.b16 {%0,%1,%2,%3}, [%4];"
                 : "=r"(r[0]), "=r"(r[1]), "=r"(r[2]), "=r"(r[3]) : "r"(a));
}
__device__ __forceinline__ void mma16816(float* c, const uint32_t* a, const uint32_t* b) {
    asm volatile(
        "mma.sync.aligned.m16n8k16.row.col.f32.bf16.bf16.f32 "
        "{%0,%1,%2,%3}, {%4,%5,%6,%7}, {%8,%9}, {%0,%1,%2,%3};"
        : "+f"(c[0]), "+f"(c[1]), "+f"(c[2]), "+f"(c[3])
        : "r"(a[0]), "r"(a[1]), "r"(a[2]), "r"(a[3]), "r"(b[0]), "r"(b[1]));
}
__device__ __forceinline__ void splitpack(float a0, float a1, uint32_t& hw, uint32_t& lw) {
    __nv_bfloat16 h0 = __float2bfloat16(a0), h1 = __float2bfloat16(a1);
    __nv_bfloat16 l0 = __float2bfloat16(a0 - __bfloat162float(h0));
    __nv_bfloat16 l1 = __float2bfloat16(a1 - __bfloat162float(h1));
    hw = (uint32_t)*(unsigned short*)&h0 | ((uint32_t)*(unsigned short*)&h1 << 16);
    lw = (uint32_t)*(unsigned short*)&l0 | ((uint32_t)*(unsigned short*)&l1 << 16);
}

// ---------------------------------------------------------------------------
// Pack fp32 -> hi/lo bf16 row-major
// ---------------------------------------------------------------------------
__global__ __launch_bounds__(256)
void pack2_k(const float* __restrict__ X, __nv_bfloat16* __restrict__ Hi,
             __nv_bfloat16* __restrict__ Lo, int n4)
{
    int i = blockIdx.x * 256 + threadIdx.x;
    if (i >= n4) return;
    float4 v = ((const float4*)X)[i];
    uint32_t h0, l0, h1, l1;
    splitpack(v.x, v.y, h0, l0);
    splitpack(v.z, v.w, h1, l1);
    *(uint2*)(Hi + 4L * i) = make_uint2(h0, h1);
    *(uint2*)(Lo + 4L * i) = make_uint2(l0, l1);
}

// Pack conv weights [o][i][7] fp32 -> [s][o][t*64+i] hi/lo
__global__ __launch_bounds__(256)
void prep_cw_k(const float* __restrict__ wq, const float* __restrict__ wk,
               const float* __restrict__ wv,
               __nv_bfloat16* __restrict__ H, __nv_bfloat16* __restrict__ L)
{
    int i = blockIdx.x * 256 + threadIdx.x;
    if (i >= 3 * 64 * 448) return;
    int k = i % 448, o = (i / 448) % 64, s = i / (64 * 448);
    int t = k >> 6, din = k & 63;
    const float* src = (s == 0) ? wq : (s == 1) ? wk : wv;
    float v = src[(o * 64 + din) * 7 + t];
    __nv_bfloat16 h = __float2bfloat16(v);
    __nv_bfloat16 l = __float2bfloat16(v - __bfloat162float(h));
    H[i] = h;
    L[i] = l;
}

// ---------------------------------------------------------------------------
// Batched HMMA GEMM, split-bf16 3-MMA.  C[m][n] = sum_k A[m][k]*B[n][k].
// MASK 0: none ; 1: AC causal skip + fused BD-shift-add epilogue (scaled) ;
//      2: BD band skip ; 3: PV K-bound.
// CMODE 0: C + z*cStride ; 1: PV scatter.
// ---------------------------------------------------------------------------
template<int BN, int CMODE, int MASK>
__global__ __launch_bounds__(256, 2)
void mma_batch_k(const __nv_bfloat16* __restrict__ Ah, const __nv_bfloat16* __restrict__ Al,
                 const __nv_bfloat16* __restrict__ Bh, const __nv_bfloat16* __restrict__ Bl,
                 float* __restrict__ C, const float* __restrict__ BDr,
                 int lda, int ldb, int ldc, int K,
                 long aStride, long bStride, int bShift, long cStride)
{
    constexpr int MATA  = 128 * 40 * 2;
    constexpr int MATB2 = BN * 40 * 2;
    constexpr int STG   = 2 * MATA + 2 * MATB2;
    constexpr int NP    = BN / 32;
    constexpr int NT8   = BN / 16;

    extern __shared__ __align__(16) unsigned char sm_raw[];
    const uint32_t sb = s2u(sm_raw);
    const int tid = threadIdx.x, lane = tid & 31, wid = tid >> 5;
    const int m0 = blockIdx.y * 128, n0 = blockIdx.x * BN;
    const int z  = blockIdx.z;
    const int wm = wid & 3, wn = wid >> 2;

    if (MASK == 1 && n0 > m0 + 127) return;
    if (MASK == 2 && m0 + n0 + 128 + BN <= 1024) return;
    if (MASK == 3) K = (K < m0 + 128) ? K : (m0 + 128);

    const __nv_bfloat16* A_h = Ah + (long)z * aStride;
    const __nv_bfloat16* A_l = Al + (long)z * aStride;
    const long boff = bShift ? (long)(z >> 2) * bStride : (long)z * bStride;
    const __nv_bfloat16* B_h = Bh + boff;
    const __nv_bfloat16* B_l = Bl + boff;
    float* Cb;
    if (CMODE == 0) Cb = C + (long)z * cStride;
    else            Cb = C + (long)(z & 3) * 1024 + (long)(z >> 2) * 64;

    const int lr = tid >> 2;
    const int lc = tid & 3;

    float acc[2][NT8][4];
#pragma unroll
    for (int a = 0; a < 2; a++)
#pragma unroll
        for (int b = 0; b < NT8; b++)
#pragma unroll
            for (int d = 0; d < 4; d++) acc[a][b][d] = 0.f;

#define STAGE_LOAD(T, BUF)                                                    \
    {                                                                         \
        uint32_t s0 = sb + (BUF) * STG;                                       \
        int k0 = (T) * 32;                                                    \
        _Pragma("unroll")                                                     \
        for (int it = 0; it < 2; it++) {                                      \
            int row = lr + it * 64;                                           \
            uint32_t so = (uint32_t)(row * 40 + lc * 8) * 2;                  \
            long ga = (long)(m0 + row) * lda + k0 + lc * 8;                   \
            cpasync16(s0 + so,        A_h + ga);                              \
            cpasync16(s0 + MATA + so, A_l + ga);                              \
        }                                                                     \
        _Pragma("unroll")                                                     \
        for (int it = 0; it < BN / 64; it++) {                                \
            int row = lr + it * 64;                                           \
            uint32_t so = (uint32_t)(row * 40 + lc * 8) * 2;                  \
            long gb = (long)(n0 + row) * ldb + k0 + lc * 8;                   \
            cpasync16(s0 + 2 * MATA + so,         B_h + gb);                  \
            cpasync16(s0 + 2 * MATA + MATB2 + so, B_l + gb);                  \
        }                                                                     \
    }

    STAGE_LOAD(0, 0)
    cp_commit();

    const int T = K / 32;
    for (int t = 0; t < T; t++) {
        const int cur = t & 1;
        if (t + 1 < T) {
            STAGE_LOAD(t + 1, cur ^ 1)
            cp_commit();
            asm volatile("cp.async.wait_group 1;" ::: "memory");
        } else {
            asm volatile("cp.async.wait_group 0;" ::: "memory");
        }
        __syncthreads();

        const uint32_t s0 = sb + cur * STG;
#pragma unroll
        for (int ks = 0; ks < 2; ks++) {
            const int k0 = ks * 16;
            uint32_t ah[2][4], al[2][4], bh[NP][4], bl[NP][4];
#pragma unroll
            for (int mt = 0; mt < 2; mt++) {
                int row = wm * 32 + mt * 16 + (lane & 15);
                int col = k0 + ((lane >> 4) << 3);
                uint32_t ao = (uint32_t)(row * 40 + col) * 2;
                ldsm4(ah[mt], s0 + ao);
                ldsm4(al[mt], s0 + MATA + ao);
            }
#pragma unroll
            for (int p = 0; p < NP; p++) {
                int row = wn * (BN / 2) + p * 16 + ((lane >> 4) << 3) + (lane & 7);
                int col = k0 + (((lane >> 3) & 1) << 3);
                uint32_t bo = (uint32_t)(row * 40 + col) * 2;
                ldsm4(bh[p], s0 + 2 * MATA + bo);
                ldsm4(bl[p], s0 + 2 * MATA + MATB2 + bo);
            }
#pragma unroll
            for (int mt = 0; mt < 2; mt++)
#pragma unroll
                for (int nt = 0; nt < NT8; nt++)
                    mma16816(acc[mt][nt], ah[mt], &bh[nt >> 1][(nt & 1) * 2]);
#pragma unroll
            for (int mt = 0; mt < 2; mt++)
#pragma unroll
                for (int nt = 0; nt < NT8; nt++)
                    mma16816(acc[mt][nt], ah[mt], &bl[nt >> 1][(nt & 1) * 2]);
#pragma unroll
            for (int mt = 0; mt < 2; mt++)
#pragma unroll
                for (int nt = 0; nt < NT8; nt++)
                    mma16816(acc[mt][nt], al[mt], &bh[nt >> 1][(nt & 1) * 2]);
        }
        __syncthreads();
    }

    if (MASK == 1) {
        // fused epilogue: score = (AC + BDraw[i][j+1023-i]) * 0.125, causal
        const float* bdz = BDr + (long)z * 1048576L;
#pragma unroll
        for (int mt = 0; mt < 2; mt++) {
            int row = m0 + wm * 32 + mt * 16 + (lane >> 2);
#pragma unroll
            for (int nt = 0; nt < NT8; nt++) {
                int col = n0 + wn * (BN / 2) + nt * 8 + (lane & 3) * 2;
#pragma unroll
                for (int rr = 0; rr < 2; rr++) {
                    int R = row + rr * 8;
#pragma unroll
                    for (int cc = 0; cc < 2; cc++) {
                        int Cc = col + cc;
                        float v = 0.f;
                        if (Cc <= R)
                            v = (acc[mt][nt][rr * 2 + cc] +
                                 bdz[(long)R * 1024 + Cc + 1023 - R]) * 0.125f;
                        Cb[(long)R * ldc + Cc] = v;
                    }
                }
            }
        }
    } else {
#pragma unroll
        for (int mt = 0; mt < 2; mt++) {
            int row = m0 + wm * 32 + mt * 16 + (lane >> 2);
#pragma unroll
            for (int nt = 0; nt < NT8; nt++) {
                int col = n0 + wn * (BN / 2) + nt * 8 + (lane & 3) * 2;
                *(float2*)(Cb + (long)row * ldc + col) =
                    make_float2(acc[mt][nt][0], acc[mt][nt][1]);
                *(float2*)(Cb + (long)(row + 8) * ldc + col) =
                    make_float2(acc[mt][nt][2], acc[mt][nt][3]);
            }
        }
    }
#undef STAGE_LOAD
}

// ---------------------------------------------------------------------------
// Conv as batched HMMA GEMM, im2col via A-side row-offset in smem.
// Per (ltile, z, s): out[l][dout] = sum_{t,din} x[l+t-3][din] * w[dout][t*64+din]
// A slab: 134 rows x 64 cols (hi/lo), pitch 72 halves. B: 64 x 448, pitch 456.
// ---------------------------------------------------------------------------
#define APITCH 72
#define BPITCH 456
#define CV_AH 0
#define CV_AL 19296
#define CV_BH 38592
#define CV_BL 96960
#define CV_SMEM 155328

__global__ __launch_bounds__(256)
void conv_mma_k(const float* __restrict__ heads,
                const __nv_bfloat16* __restrict__ cwh, const __nv_bfloat16* __restrict__ cwl,
                const float* __restrict__ cbq, const float* __restrict__ cbk,
                const float* __restrict__ cbv,
                const float* __restrict__ rwb, const float* __restrict__ rrb,
                __nv_bfloat16* __restrict__ qwh, __nv_bfloat16* __restrict__ qwl,
                __nv_bfloat16* __restrict__ qrh, __nv_bfloat16* __restrict__ qrl,
                __nv_bfloat16* __restrict__ khh, __nv_bfloat16* __restrict__ khl,
                __nv_bfloat16* __restrict__ vhh, __nv_bfloat16* __restrict__ vhl)
{
    extern __shared__ __align__(16) unsigned char sm_raw[];
    const uint32_t sb = s2u(sm_raw);
    const int tid = threadIdx.x, lane = tid & 31, wid = tid >> 5;
    const int l0 = blockIdx.x * 128;
    const int z  = blockIdx.y;          // h*4 + b
    const int s  = blockIdx.z;
    const int h  = z >> 2, b = z & 3;
    const int wm = wid & 3, wn = wid >> 2;

    // B weights -> smem via cp.async (hi/lo)
    const __nv_bfloat16* wph = cwh + (long)s * (64 * 448);
    const __nv_bfloat16* wpl = cwl + (long)s * (64 * 448);
    for (int i = tid; i < 64 * 56; i += 256) {
        int o = i / 56, c = i % 56;
        uint32_t so = (uint32_t)(o * BPITCH + c * 8) * 2;
        cpasync16(sb + CV_BH + so, wph + o * 448 + c * 8);
        cpasync16(sb + CV_BL + so, wpl + o * 448 + c * 8);
    }
    cp_commit();

    // A slab: rows l0-3 .. l0+130 of heads slice, fp32 -> hi/lo bf16
    const float* hsrc = heads + (long)b * 3072 + s * 1024 + h * 64;
    for (int i = tid; i < 134 * 16; i += 256) {
        int r = i / 16, c4 = i % 16;
        int lg = l0 - 3 + r;
        float4 v = make_float4(0.f, 0.f, 0.f, 0.f);
        if (lg >= 0 && lg < 1024)
            v = *(const float4*)(hsrc + (long)lg * 4 * 3072 + c4 * 4);
        uint32_t h0, lw0, h1, lw1;
        splitpack(v.x, v.y, h0, lw0);
        splitpack(v.z, v.w, h1, lw1);
        uint32_t off = (uint32_t)(r * APITCH + c4 * 4) * 2;
        *(uint2*)(sm_raw + CV_AH + off) = make_uint2(h0, h1);
        *(uint2*)(sm_raw + CV_AL + off) = make_uint2(lw0, lw1);
    }
    asm volatile("cp.async.wait_group 0;" ::: "memory");
    __syncthreads();

    float acc[2][4][4];
#pragma unroll
    for (int a = 0; a < 2; a++)
#pragma unroll
        for (int c = 0; c < 4; c++)
#pragma unroll
            for (int d = 0; d < 4; d++) acc[a][c][d] = 0.f;

    for (int t = 0; t < 7; t++) {
#pragma unroll
        for (int dk = 0; dk < 4; dk++) {
            uint32_t ah[2][4], al[2][4], bh[2][4], bl[2][4];
#pragma unroll
            for (int mt = 0; mt < 2; mt++) {
                int row = wm * 32 + mt * 16 + (lane & 15) + t;   // tap offset!
                int col = dk * 16 + ((lane >> 4) << 3);
                uint32_t ao = (uint32_t)(row * APITCH + col) * 2;
                ldsm4(ah[mt], sb + CV_AH + ao);
                ldsm4(al[mt], sb + CV_AL + ao);
            }
#pragma unroll
            for (int p = 0; p < 2; p++) {
                int row = wn * 32 + p * 16 + ((lane >> 4) << 3) + (lane & 7);
                int col = t * 64 + dk * 16 + (((lane >> 3) & 1) << 3);
                uint32_t bo = (uint32_t)(row * BPITCH + col) * 2;
                ldsm4(bh[p], sb + CV_BH + bo);
                ldsm4(bl[p], sb + CV_BL + bo);
            }
#pragma unroll
            for (int mt = 0; mt < 2; mt++)
#pragma unroll
                for (int nt = 0; nt < 4; nt++)
                    mma16816(acc[mt][nt], ah[mt], &bh[nt >> 1][(nt & 1) * 2]);
#pragma unroll
            for (int mt = 0; mt < 2; mt++)
#pragma unroll
                for (int nt = 0; nt < 4; nt++)
                    mma16816(acc[mt][nt], ah[mt], &bl[nt >> 1][(nt & 1) * 2]);
#pragma unroll
            for (int mt = 0; mt < 2; mt++)
#pragma unroll
                for (int nt = 0; nt < 4; nt++)
                    mma16816(acc[mt][nt], al[mt], &bh[nt >> 1][(nt & 1) * 2]);
        }
    }

    if (s == 2) {
        // stage v into smem fp32 [128][68], then write transposed [z][d][l]
        __syncthreads();
        float* stg = (float*)sm_raw;
#pragma unroll
        for (int mt = 0; mt < 2; mt++) {
            int rl = wm * 32 + mt * 16 + (lane >> 2);
#pragma unroll
            for (int nt = 0; nt < 4; nt++) {
                int cd = wn * 32 + nt * 8 + (lane & 3) * 2;
                float b0 = cbv[cd], b1 = cbv[cd + 1];
                stg[rl * 68 + cd]           = acc[mt][nt][0] + b0;
                stg[rl * 68 + cd + 1]       = acc[mt][nt][1] + b1;
                stg[(rl + 8) * 68 + cd]     = acc[mt][nt][2] + b0;
                stg[(rl + 8) * 68 + cd + 1] = acc[mt][nt][3] + b1;
            }
        }
        __syncthreads();
        const int d  = tid >> 2;
        const int lb = (tid & 3) * 32;
        long ob = ((long)z * 64 + d) * 1024 + l0 + lb;
#pragma unroll
        for (int j = 0; j < 32; j += 2) {
            float v0 = stg[(lb + j) * 68 + d];
            float v1 = stg[(lb + j + 1) * 68 + d];
            uint32_t hw, lw;
            splitpack(v0, v1, hw, lw);
            *(uint32_t*)(vhh + ob + j) = hw;
            *(uint32_t*)(vhl + ob + j) = lw;
        }
        return;
    }

    // q/k: write [z][l][d] directly from fragments
#pragma unroll
    for (int mt = 0; mt < 2; mt++) {
        int rl = wm * 32 + mt * 16 + (lane >> 2);
#pragma unroll
        for (int nt = 0; nt < 4; nt++) {
            int cd = wn * 32 + nt * 8 + (lane & 3) * 2;
#pragma unroll
            for (int rr = 0; rr < 2; rr++) {
                int R = rl + rr * 8;
                long ob = ((long)z * 1024 + l0 + R) * 64 + cd;
                float v0 = acc[mt][nt][rr * 2 + 0];
                float v1 = acc[mt][nt][rr * 2 + 1];
                uint32_t hw, lw;
                if (s == 0) {
                    float c0 = cbq[cd], c1 = cbq[cd + 1];
                    splitpack(v0 + c0 + rwb[h * 64 + cd], v1 + c1 + rwb[h * 64 + cd + 1], hw, lw);
                    *(uint32_t*)(qwh + ob) = hw;
                    *(uint32_t*)(qwl + ob) = lw;
                    splitpack(v0 + c0 + rrb[h * 64 + cd], v1 + c1 + rrb[h * 64 + cd + 1], hw, lw);
                    *(uint32_t*)(qrh + ob) = hw;
                    *(uint32_t*)(qrl + ob) = lw;
                } else {
                    splitpack(v0 + cbk[cd], v1 + cbk[cd + 1], hw, lw);
                    *(uint32_t*)(khh + ob) = hw;
                    *(uint32_t*)(khl + ob) = lw;
                }
            }
        }
    }
}

// ---------------------------------------------------------------------------
// SIMT SGEMM (rproj only)
// ---------------------------------------------------------------------------
template<int BM,int BN,int BK,int TM,int TN>
__global__ __launch_bounds__((BM/TM)*(BN/TN))
void gemm_k(const float* __restrict__ A, const float* __restrict__ B,
            float* __restrict__ C, int K, int lda, int ldb, int ldc)
{
    constexpr int TX = BN / TN;
    constexpr int TY = BM / TM;
    constexpr int NT = TX * TY;
    constexpr int NA = BM * BK / 4;
    constexpr int NB = BN * BK / 4;
    constexpr int LA = (NA + NT - 1) / NT;
    constexpr int LB = (NB + NT - 1) / NT;

    const int tid = threadIdx.x;
    const int m0  = blockIdx.y * BM;
    const int n0  = blockIdx.x * BN;

    __shared__ float As[2][BK][BM + 4];
    __shared__ float Bs[2][BK][BN + 4];

    const int tx = tid % TX;
    const int ty = tid / TX;

    float acc[TM][TN];
#pragma unroll
    for (int i = 0; i < TM; i++)
#pragma unroll
        for (int j = 0; j < TN; j++) acc[i][j] = 0.f;

    float4 ra[LA], rb[LB];

#define LOAD_AB(K0)                                                            \
    _Pragma("unroll")                                                          \
    for (int u = 0; u < LA; u++) {                                             \
        int i = tid + u * NT;                                                  \
        int r = i / (BK/4), q = i % (BK/4);                                    \
        ra[u] = *(const float4*)(A + (long)(m0 + r) * lda + (K0) + q*4);       \
    }                                                                          \
    _Pragma("unroll")                                                          \
    for (int u = 0; u < LB; u++) {                                             \
        int i = tid + u * NT;                                                  \
        int r = i / (BK/4), q = i % (BK/4);                                    \
        rb[u] = *(const float4*)(B + (long)(n0 + r) * ldb + (K0) + q*4);       \
    }
#define STORE_AB(BUF)                                                          \
    _Pragma("unroll")                                                          \
    for (int u = 0; u < LA; u++) {                                             \
        int i = tid + u * NT;                                                  \
        int r = i / (BK/4), q = i % (BK/4);                                    \
        As[BUF][q*4+0][r] = ra[u].x; As[BUF][q*4+1][r] = ra[u].y;              \
        As[BUF][q*4+2][r] = ra[u].z; As[BUF][q*4+3][r] = ra[u].w;              \
    }                                                                          \
    _Pragma("unroll")                                                          \
    for (int u = 0; u < LB; u++) {                                             \
        int i = tid + u * NT;                                                  \
        int r = i / (BK/4), q = i % (BK/4);                                    \
        Bs[BUF][q*4+0][r] = rb[u].x; Bs[BUF][q*4+1][r] = rb[u].y;              \
        Bs[BUF][q*4+2][r] = rb[u].z; Bs[BUF][q*4+3][r] = rb[u].w;              \
    }

    LOAD_AB(0)
    STORE_AB(0)
    __syncthreads();

    const int ktiles = K / BK;
    for (int t = 0; t < ktiles; t++) {
        const int cur = t & 1;
        if (t + 1 < ktiles) { LOAD_AB((t + 1) * BK) }
#pragma unroll
        for (int kk = 0; kk < BK; kk++) {
            float a[TM], bb[TN];
#pragma unroll
            for (int u = 0; u < TM / 4; u++)
                *(float4*)&a[u * 4] = *(const float4*)&As[cur][kk][ty * TM + u * 4];
#pragma unroll
            for (int u = 0; u < TN / 4; u++)
                *(float4*)&bb[u * 4] = *(const float4*)&Bs[cur][kk][tx * TN + u * 4];
#pragma unroll
            for (int i = 0; i < TM; i++)
#pragma unroll
                for (int j = 0; j < TN; j++)
                    acc[i][j] += a[i] * bb[j];
        }
        if (t + 1 < ktiles) {
            STORE_AB(cur ^ 1)
            __syncthreads();
        }
    }

#pragma unroll
    for (int i = 0; i < TM; i++) {
        long row = m0 + ty * TM + i;
#pragma unroll
        for (int u = 0; u < TN / 4; u++) {
            float4 v = make_float4(acc[i][u*4+0], acc[i][u*4+1],
                                   acc[i][u*4+2], acc[i][u*4+3]);
            *(float4*)(C + row * ldc + n0 + tx * TN + u * 4) = v;
        }
    }
#undef LOAD_AB
#undef STORE_AB
}

// ---------------------------------------------------------------------------
// Softmax over fused scaled scores; writes prob hi/lo only up to the
// 128-aligned causal bound (exactly what PV's K-bound reads).
// ---------------------------------------------------------------------------
__global__ __launch_bounds__(256)
void softmax_k(float* __restrict__ scbuf,
               __nv_bfloat16* __restrict__ ph, __nv_bfloat16* __restrict__ pl)
{
    const int i = blockIdx.x;
    const int z = blockIdx.y;
    float* sc = scbuf + (long)z * (1024L * 1024) + (long)i * 1024;
    const int n = i + 1;
    const int jlim = ((i >> 7) + 1) << 7;
    __shared__ float red[8];
    const int tid = threadIdx.x;
    const int lane = tid & 31, wid = tid >> 5;

    float mx = -1e30f;
    for (int j = tid; j < n; j += 256)
        mx = fmaxf(mx, sc[j]);
#pragma unroll
    for (int o = 16; o > 0; o >>= 1)
        mx = fmaxf(mx, __shfl_xor_sync(0xffffffffu, mx, o));
    if (lane == 0) red[wid] = mx;
    __syncthreads();
    if (tid == 0) {
        float m = red[0];
#pragma unroll
        for (int k = 1; k < 8; k++) m = fmaxf(m, red[k]);
        red[0] = m;
    }
    __syncthreads();
    const float MX = red[0];
    __syncthreads();

    float sum = 0.f;
    for (int j = tid; j < n; j += 256) {
        float e = __expf(sc[j] - MX);
        sc[j] = e;
        sum += e;
    }
#pragma unroll
    for (int o = 16; o > 0; o >>= 1)
        sum += __shfl_xor_sync(0xffffffffu, sum, o);
    if (lane == 0) red[wid] = sum;
    __syncthreads();
    if (tid == 0) {
        float sm = 0.f;
#pragma unroll
        for (int k = 0; k < 8; k++) sm += red[k];
        red[0] = 1.f / sm;
    }
    __syncthreads();
    const float inv = red[0];

    const int j0 = tid * 4;
    if (j0 < jlim) {
        float p0 = (j0 + 0 < n) ? sc[j0 + 0] * inv : 0.f;
        float p1 = (j0 + 1 < n) ? sc[j0 + 1] * inv : 0.f;
        float p2 = (j0 + 2 < n) ? sc[j0 + 2] * inv : 0.f;
        float p3 = (j0 + 3 < n) ? sc[j0 + 3] * inv : 0.f;
        uint32_t h0, l0, h1, l1;
        splitpack(p0, p1, h0, l0);
        splitpack(p2, p3, h1, l1);
        long idx = (long)z * (1024L * 1024) + (long)i * 1024 + j0;
        *(uint2*)(ph + idx) = make_uint2(h0, h1);
        *(uint2*)(pl + idx) = make_uint2(l0, l1);
    }
}

// ---------------------------------------------------------------------------
// Fused residual + LayerNorm
// ---------------------------------------------------------------------------
__global__ __launch_bounds__(256)
void ln_k(const float* __restrict__ w, const float* __restrict__ attn,
          const float* __restrict__ gamma, const float* __restrict__ beta,
          float* __restrict__ out)
{
    const long t = blockIdx.x;
    __shared__ float xs[1024];
    __shared__ float red[8];
    const int tid = threadIdx.x, lane = tid & 31, wid = tid >> 5;

    float s = 0.f;
    for (int j = tid; j < 1024; j += 256) {
        float v = w[t * 1024 + j] + attn[t * 1024 + j];
        xs[j] = v;
        s += v;
    }
#pragma unroll
    for (int o = 16; o > 0; o >>= 1) s += __shfl_xor_sync(0xffffffffu, s, o);
    if (lane == 0) red[wid] = s;
    __syncthreads();
    if (tid == 0) {
        float tot = 0.f;
#pragma unroll
        for (int k = 0; k < 8; k++) tot += red[k];
        red[0] = tot * (1.f / 1024.f);
    }
    __syncthreads();
    const float mu = red[0];
    __syncthreads();

    float vs = 0.f;
    for (int j = tid; j < 1024; j += 256) {
        float d = xs[j] - mu;
        vs += d * d;
    }
#pragma unroll
    for (int o = 16; o > 0; o >>= 1) vs += __shfl_xor_sync(0xffffffffu, vs, o);
    if (lane == 0) red[wid] = vs;
    __syncthreads();
    if (tid == 0) {
        float tot = 0.f;
#pragma unroll
        for (int k = 0; k < 8; k++) tot += red[k];
        red[0] = rsqrtf(tot * (1.f / 1024.f) + 1e-5f);
    }
    __syncthreads();
    const float rstd = red[0];
    for (int j = tid; j < 1024; j += 256)
        out[t * 1024 + j] = (xs[j] - mu) * rstd * gamma[j] + beta[j];
}

// ---------------------------------------------------------------------------
// Orchestration
// ---------------------------------------------------------------------------
extern "C" void kernel_launch(void* const* d_in, const int* in_sizes, int n_in,
                              void* d_out, int out_size)
{
    (void)in_sizes; (void)n_in; (void)out_size;
    const float* w     = (const float*)d_in[0];
    const float* r     = (const float*)d_in[1];
    const float* rwb   = (const float*)d_in[2];
    const float* rrb   = (const float*)d_in[3];
    const float* Wqkv  = (const float*)d_in[4];
    const float* Wr    = (const float*)d_in[5];
    const float* Wo    = (const float*)d_in[6];
    const float* cwq   = (const float*)d_in[7];
    const float* cbq   = (const float*)d_in[8];
    const float* cwk   = (const float*)d_in[9];
    const float* cbk   = (const float*)d_in[10];
    const float* cwv   = (const float*)d_in[11];
    const float* cbv   = (const float*)d_in[12];
    const float* gamma = (const float*)d_in[13];
    const float* beta  = (const float*)d_in[14];
    float* out = (float*)d_out;

    float *heads, *rproj, *ac, *bd, *vec, *attn;
    __nv_bfloat16 *ahi, *alo, *bhi, *blo, *whi, *wlo, *cwh, *cwl;
    __nv_bfloat16 *qwh, *qwl, *qrh, *qrl, *khh, *khl, *vhh, *vhl, *rph, *rpl, *ph, *pl;
    cudaGetSymbolAddress((void**)&heads,  g_heads);
    cudaGetSymbolAddress((void**)&rproj,  g_rproj);
    cudaGetSymbolAddress((void**)&ac,     g_ac);
    cudaGetSymbolAddress((void**)&bd,     g_bd);
    cudaGetSymbolAddress((void**)&vec,    g_vec);
    cudaGetSymbolAddress((void**)&attn,   g_attn);
    cudaGetSymbolAddress((void**)&ahi,    g_ahi);
    cudaGetSymbolAddress((void**)&alo,    g_alo);
    cudaGetSymbolAddress((void**)&bhi,    g_bhi);
    cudaGetSymbolAddress((void**)&blo,    g_blo);
    cudaGetSymbolAddress((void**)&whi,    g_whi);
    cudaGetSymbolAddress((void**)&wlo,    g_wlo);
    cudaGetSymbolAddress((void**)&cwh,    g_cwh);
    cudaGetSymbolAddress((void**)&cwl,    g_cwl);
    cudaGetSymbolAddress((void**)&qwh,    g_qwh);
    cudaGetSymbolAddress((void**)&qwl,    g_qwl);
    cudaGetSymbolAddress((void**)&qrh,    g_qrh);
    cudaGetSymbolAddress((void**)&qrl,    g_qrl);
    cudaGetSymbolAddress((void**)&khh,    g_khh);
    cudaGetSymbolAddress((void**)&khl,    g_khl);
    cudaGetSymbolAddress((void**)&vhh,    g_vhh);
    cudaGetSymbolAddress((void**)&vhl,    g_vhl);
    cudaGetSymbolAddress((void**)&rph,    g_rph);
    cudaGetSymbolAddress((void**)&rpl,    g_rpl);
    cudaGetSymbolAddress((void**)&ph,     g_ph);
    cudaGetSymbolAddress((void**)&pl,     g_pl);

    const int SM128 = 2 * (2 * 128 * 40 * 2 + 2 * 128 * 40 * 2);
    const int SM64  = 2 * (2 * 128 * 40 * 2 + 2 *  64 * 40 * 2);
    cudaFuncSetAttribute(mma_batch_k<128,0,0>, cudaFuncAttributeMaxDynamicSharedMemorySize, SM128);
    cudaFuncSetAttribute(mma_batch_k<128,0,1>, cudaFuncAttributeMaxDynamicSharedMemorySize, SM128);
    cudaFuncSetAttribute(mma_batch_k<128,0,2>, cudaFuncAttributeMaxDynamicSharedMemorySize, SM128);
    cudaFuncSetAttribute(mma_batch_k<64,1,3>,  cudaFuncAttributeMaxDynamicSharedMemorySize, SM64);
    cudaFuncSetAttribute(conv_mma_k, cudaFuncAttributeMaxDynamicSharedMemorySize, CV_SMEM);

    // 1. packs
    pack2_k<<<4096, 256>>>(w,    ahi, alo, 4096 * 256);
    pack2_k<<<3072, 256>>>(Wqkv, bhi, blo, 3072 * 256);
    pack2_k<<<1024, 256>>>(Wo,   whi, wlo, 1024 * 256);
    prep_cw_k<<<(3 * 64 * 448 + 255) / 256, 256>>>(cwq, cwk, cwv, cwh, cwl);

    // 2. heads = w @ Wqkv^T (HMMA)
    mma_batch_k<128,0,0><<<dim3(24, 32, 1), 256, SM128>>>(
        ahi, alo, bhi, blo, heads, nullptr, 1024, 1024, 3072, 1024, 0, 0, 0, 0);

    // 3. rproj = r @ Wr^T + pack
    gemm_k<128,128,8,8,8><<<dim3(8, 8, 1), 256>>>(r, Wr, rproj, 1024, 1024, 1024, 1024);
    pack2_k<<<1024, 256>>>(rproj, rph, rpl, 1024 * 256);

    // 4. conv as HMMA GEMM (reads heads directly; emits all attention operands)
    conv_mma_k<<<dim3(8, 64, 3), 256, CV_SMEM>>>(
        heads, cwh, cwl, cbq, cbk, cbv, rwb, rrb,
        qwh, qwl, qrh, qrl, khh, khl, vhh, vhl);

    // 5. BD raw (HMMA, band skip)
    mma_batch_k<128,0,2><<<dim3(8, 8, 64), 256, SM128>>>(
        qrh, qrl, rph, rpl, bd, nullptr, 64, 1024, 1024, 64, 65536L, 64L, 1, 1048576L);

    // 6. AC + fused BD-shift-add + scale (HMMA, causal skip)
    mma_batch_k<128,0,1><<<dim3(8, 8, 64), 256, SM128>>>(
        qwh, qwl, khh, khl, ac, bd, 64, 64, 1024, 64, 65536L, 65536L, 0, 1048576L);

    // 7. softmax -> prob hi/lo (bounded writes)
    softmax_k<<<dim3(1024, 64), 256>>>(ac, ph, pl);

    // 8. PV (HMMA, K-bounded, scatter epilogue)
    mma_batch_k<64,1,3><<<dim3(1, 8, 64), 256, SM64>>>(
        ph, pl, vhh, vhl, vec, nullptr, 1024, 1024, 4096, 1024, 1048576L, 65536L, 0, 0);

    // 9. attn = vec @ Wo^T (HMMA)
    pack2_k<<<4096, 256>>>(vec, ahi, alo, 4096 * 256);
    mma_batch_k<128,0,0><<<dim3(8, 32, 1), 256, SM128>>>(
        ahi, alo, whi, wlo, attn, nullptr, 1024, 1024, 1024, 1024, 0, 0, 0, 0);

    // 10. out = LayerNorm(w + attn)
    ln_k<<<4096, 256>>>(w, attn, gamma, beta, out);
}

// round 16
// speedup vs baseline: 2.5092x; 1.0898x over previous
#include <cuda_runtime.h>
#include <cuda_bf16.h>
#include <cstdint>

// ---------------------------------------------------------------------------
// Problem constants
// ---------------------------------------------------------------------------
#define QLEN  1024
#define BSZ   4
#define NH    16
#define DH    64
#define DM    1024
#define NTOK  4096
#define NBH   64

// ---------------------------------------------------------------------------
// Device scratch
// ---------------------------------------------------------------------------
__device__ float g_heads [(long)NTOK * 3072];
__device__ float g_rproj [(long)QLEN * DM];
__device__ float g_bd    [(long)NBH * QLEN * QLEN];   // raw BD
__device__ float g_attn  [(long)NTOK * DM];

// Split-bf16 operands
__device__ __align__(16) __nv_bfloat16 g_ahi[(long)4096 * 1024];
__device__ __align__(16) __nv_bfloat16 g_alo[(long)4096 * 1024];
__device__ __align__(16) __nv_bfloat16 g_bhi[(long)3072 * 1024];
__device__ __align__(16) __nv_bfloat16 g_blo[(long)3072 * 1024];
__device__ __align__(16) __nv_bfloat16 g_whi[(long)1024 * 1024];
__device__ __align__(16) __nv_bfloat16 g_wlo[(long)1024 * 1024];
// conv weights packed [s][dout][t*64+din], hi/lo
__device__ __align__(16) __nv_bfloat16 g_cwh[3 * 64 * 448];
__device__ __align__(16) __nv_bfloat16 g_cwl[3 * 64 * 448];
// attention operands
__device__ __align__(16) __nv_bfloat16 g_qwh[(long)NBH * QLEN * DH];  // [z][l][d]
__device__ __align__(16) __nv_bfloat16 g_qwl[(long)NBH * QLEN * DH];
__device__ __align__(16) __nv_bfloat16 g_qrh[(long)NBH * QLEN * DH];
__device__ __align__(16) __nv_bfloat16 g_qrl[(long)NBH * QLEN * DH];
__device__ __align__(16) __nv_bfloat16 g_khh[(long)NBH * QLEN * DH];
__device__ __align__(16) __nv_bfloat16 g_khl[(long)NBH * QLEN * DH];
__device__ __align__(16) __nv_bfloat16 g_vhh[(long)NBH * DH * QLEN];  // [z][d][l]
__device__ __align__(16) __nv_bfloat16 g_vhl[(long)NBH * DH * QLEN];
__device__ __align__(16) __nv_bfloat16 g_rph[(long)QLEN * DM];
__device__ __align__(16) __nv_bfloat16 g_rpl[(long)QLEN * DM];

// ---------------------------------------------------------------------------
// Baseline-PTX helpers (plain sm_103)
// ---------------------------------------------------------------------------
__device__ __forceinline__ uint32_t s2u(const void* p) {
    uint32_t a;
    asm("{ .reg .u64 t; cvta.to.shared.u64 t, %1; cvt.u32.u64 %0, t; }"
        : "=r"(a) : "l"(p));
    return a;
}
__device__ __forceinline__ void cpasync16(uint32_t dst, const void* src) {
    asm volatile("cp.async.cg.shared.global [%0], [%1], 16;" :: "r"(dst), "l"(src));
}
__device__ __forceinline__ void cp_commit() {
    asm volatile("cp.async.commit_group;" ::: "memory");
}
__device__ __forceinline__ void ldsm4(uint32_t* r, uint32_t a) {
    asm volatile("ldmatrix.sync.aligned.m8n8.x4.shared.b16 {%0,%1,%2,%3}, [%4];"
                 : "=r"(r[0]), "=r"(r[1]), "=r"(r[2]), "=r"(r[3]) : "r"(a));
}
__device__ __forceinline__ void mma16816(float* c, const uint32_t* a, const uint32_t* b) {
    asm volatile(
        "mma.sync.aligned.m16n8k16.row.col.f32.bf16.bf16.f32 "
        "{%0,%1,%2,%3}, {%4,%5,%6,%7}, {%8,%9}, {%0,%1,%2,%3};"
        : "+f"(c[0]), "+f"(c[1]), "+f"(c[2]), "+f"(c[3])
        : "r"(a[0]), "r"(a[1]), "r"(a[2]), "r"(a[3]), "r"(b[0]), "r"(b[1]));
}
__device__ __forceinline__ void splitpack(float a0, float a1, uint32_t& hw, uint32_t& lw) {
    __nv_bfloat16 h0 = __float2bfloat16(a0), h1 = __float2bfloat16(a1);
    __nv_bfloat16 l0 = __float2bfloat16(a0 - __bfloat162float(h0));
    __nv_bfloat16 l1 = __float2bfloat16(a1 - __bfloat162float(h1));
    hw = (uint32_t)*(unsigned short*)&h0 | ((uint32_t)*(unsigned short*)&h1 << 16);
    lw = (uint32_t)*(unsigned short*)&l0 | ((uint32_t)*(unsigned short*)&l1 << 16);
}

// ---------------------------------------------------------------------------
// Pack fp32 -> hi/lo bf16 row-major
// ---------------------------------------------------------------------------
__global__ __launch_bounds__(256)
void pack2_k(const float* __restrict__ X, __nv_bfloat16* __restrict__ Hi,
             __nv_bfloat16* __restrict__ Lo, int n4)
{
    int i = blockIdx.x * 256 + threadIdx.x;
    if (i >= n4) return;
    float4 v = ((const float4*)X)[i];
    uint32_t h0, l0, h1, l1;
    splitpack(v.x, v.y, h0, l0);
    splitpack(v.z, v.w, h1, l1);
    *(uint2*)(Hi + 4L * i) = make_uint2(h0, h1);
    *(uint2*)(Lo + 4L * i) = make_uint2(l0, l1);
}

// Pack conv weights [o][i][7] fp32 -> [s][o][t*64+i] hi/lo
__global__ __launch_bounds__(256)
void prep_cw_k(const float* __restrict__ wq, const float* __restrict__ wk,
               const float* __restrict__ wv,
               __nv_bfloat16* __restrict__ H, __nv_bfloat16* __restrict__ L)
{
    int i = blockIdx.x * 256 + threadIdx.x;
    if (i >= 3 * 64 * 448) return;
    int k = i % 448, o = (i / 448) % 64, s = i / (64 * 448);
    int t = k >> 6, din = k & 63;
    const float* src = (s == 0) ? wq : (s == 1) ? wk : wv;
    float v = src[(o * 64 + din) * 7 + t];
    __nv_bfloat16 h = __float2bfloat16(v);
    __nv_bfloat16 l = __float2bfloat16(v - __bfloat162float(h));
    H[i] = h;
    L[i] = l;
}

// ---------------------------------------------------------------------------
// Batched HMMA GEMM, split-bf16 3-MMA.  C[m][n] = sum_k A[m][k]*B[n][k].
// MASK 0: none ; 2: BD band skip.
// ---------------------------------------------------------------------------
template<int BN, int MASK>
__global__ __launch_bounds__(256, 2)
void mma_batch_k(const __nv_bfloat16* __restrict__ Ah, const __nv_bfloat16* __restrict__ Al,
                 const __nv_bfloat16* __restrict__ Bh, const __nv_bfloat16* __restrict__ Bl,
                 float* __restrict__ C,
                 int lda, int ldb, int ldc, int K,
                 long aStride, long bStride, int bShift, long cStride)
{
    constexpr int MATA  = 128 * 40 * 2;
    constexpr int MATB2 = BN * 40 * 2;
    constexpr int STG   = 2 * MATA + 2 * MATB2;
    constexpr int NP    = BN / 32;
    constexpr int NT8   = BN / 16;

    extern __shared__ __align__(16) unsigned char sm_raw[];
    const uint32_t sb = s2u(sm_raw);
    const int tid = threadIdx.x, lane = tid & 31, wid = tid >> 5;
    const int m0 = blockIdx.y * 128, n0 = blockIdx.x * BN;
    const int z  = blockIdx.z;
    const int wm = wid & 3, wn = wid >> 2;

    if (MASK == 2 && m0 + n0 + 128 + BN <= 1024) return;

    const __nv_bfloat16* A_h = Ah + (long)z * aStride;
    const __nv_bfloat16* A_l = Al + (long)z * aStride;
    const long boff = bShift ? (long)(z >> 2) * bStride : (long)z * bStride;
    const __nv_bfloat16* B_h = Bh + boff;
    const __nv_bfloat16* B_l = Bl + boff;
    float* Cb = C + (long)z * cStride;

    const int lr = tid >> 2;
    const int lc = tid & 3;

    float acc[2][NT8][4];
#pragma unroll
    for (int a = 0; a < 2; a++)
#pragma unroll
        for (int b = 0; b < NT8; b++)
#pragma unroll
            for (int d = 0; d < 4; d++) acc[a][b][d] = 0.f;

#define STAGE_LOAD(T, BUF)                                                    \
    {                                                                         \
        uint32_t s0 = sb + (BUF) * STG;                                       \
        int k0 = (T) * 32;                                                    \
        _Pragma("unroll")                                                     \
        for (int it = 0; it < 2; it++) {                                      \
            int row = lr + it * 64;                                           \
            uint32_t so = (uint32_t)(row * 40 + lc * 8) * 2;                  \
            long ga = (long)(m0 + row) * lda + k0 + lc * 8;                   \
            cpasync16(s0 + so,        A_h + ga);                              \
            cpasync16(s0 + MATA + so, A_l + ga);                              \
        }                                                                     \
        _Pragma("unroll")                                                     \
        for (int it = 0; it < BN / 64; it++) {                                \
            int row = lr + it * 64;                                           \
            uint32_t so = (uint32_t)(row * 40 + lc * 8) * 2;                  \
            long gb = (long)(n0 + row) * ldb + k0 + lc * 8;                   \
            cpasync16(s0 + 2 * MATA + so,         B_h + gb);                  \
            cpasync16(s0 + 2 * MATA + MATB2 + so, B_l + gb);                  \
        }                                                                     \
    }

    STAGE_LOAD(0, 0)
    cp_commit();

    const int T = K / 32;
    for (int t = 0; t < T; t++) {
        const int cur = t & 1;
        if (t + 1 < T) {
            STAGE_LOAD(t + 1, cur ^ 1)
            cp_commit();
            asm volatile("cp.async.wait_group 1;" ::: "memory");
        } else {
            asm volatile("cp.async.wait_group 0;" ::: "memory");
        }
        __syncthreads();

        const uint32_t s0 = sb + cur * STG;
#pragma unroll
        for (int ks = 0; ks < 2; ks++) {
            const int k0 = ks * 16;
            uint32_t ah[2][4], al[2][4], bh[NP][4], bl[NP][4];
#pragma unroll
            for (int mt = 0; mt < 2; mt++) {
                int row = wm * 32 + mt * 16 + (lane & 15);
                int col = k0 + ((lane >> 4) << 3);
                uint32_t ao = (uint32_t)(row * 40 + col) * 2;
                ldsm4(ah[mt], s0 + ao);
                ldsm4(al[mt], s0 + MATA + ao);
            }
#pragma unroll
            for (int p = 0; p < NP; p++) {
                int row = wn * (BN / 2) + p * 16 + ((lane >> 4) << 3) + (lane & 7);
                int col = k0 + (((lane >> 3) & 1) << 3);
                uint32_t bo = (uint32_t)(row * 40 + col) * 2;
                ldsm4(bh[p], s0 + 2 * MATA + bo);
                ldsm4(bl[p], s0 + 2 * MATA + MATB2 + bo);
            }
#pragma unroll
            for (int mt = 0; mt < 2; mt++)
#pragma unroll
                for (int nt = 0; nt < NT8; nt++)
                    mma16816(acc[mt][nt], ah[mt], &bh[nt >> 1][(nt & 1) * 2]);
#pragma unroll
            for (int mt = 0; mt < 2; mt++)
#pragma unroll
                for (int nt = 0; nt < NT8; nt++)
                    mma16816(acc[mt][nt], ah[mt], &bl[nt >> 1][(nt & 1) * 2]);
#pragma unroll
            for (int mt = 0; mt < 2; mt++)
#pragma unroll
                for (int nt = 0; nt < NT8; nt++)
                    mma16816(acc[mt][nt], al[mt], &bh[nt >> 1][(nt & 1) * 2]);
        }
        __syncthreads();
    }

#pragma unroll
    for (int mt = 0; mt < 2; mt++) {
        int row = m0 + wm * 32 + mt * 16 + (lane >> 2);
#pragma unroll
        for (int nt = 0; nt < NT8; nt++) {
            int col = n0 + wn * (BN / 2) + nt * 8 + (lane & 3) * 2;
            *(float2*)(Cb + (long)row * ldc + col) =
                make_float2(acc[mt][nt][0], acc[mt][nt][1]);
            *(float2*)(Cb + (long)(row + 8) * ldc + col) =
                make_float2(acc[mt][nt][2], acc[mt][nt][3]);
        }
    }
#undef STAGE_LOAD
}

// ---------------------------------------------------------------------------
// Fused flash attention: S=QK^T (HMMA) + BD-shift-add-scale + causal mask +
// online softmax (in-warp) + PV (HMMA).  One CTA per (itile, z).
// Output written as split-bf16 directly into Wo's packed A operand.
// ---------------------------------------------------------------------------
#define FL_KBYTES (128 * 72 * 2)
#define FL_VBYTES (64 * 136 * 2)
#define FL_KH 0
#define FL_KL FL_KBYTES
#define FL_VH (2 * FL_KBYTES)
#define FL_VL (2 * FL_KBYTES + FL_VBYTES)
#define FL_STG (2 * FL_KBYTES + 2 * FL_VBYTES)
#define FL_SMEM (2 * FL_STG)

__global__ __launch_bounds__(256)
void flash_k(const __nv_bfloat16* __restrict__ Qh_, const __nv_bfloat16* __restrict__ Ql_,
             const __nv_bfloat16* __restrict__ Kh_, const __nv_bfloat16* __restrict__ Kl_,
             const __nv_bfloat16* __restrict__ Vh_, const __nv_bfloat16* __restrict__ Vl_,
             const float* __restrict__ bd,
             __nv_bfloat16* __restrict__ outh, __nv_bfloat16* __restrict__ outl)
{
    extern __shared__ __align__(16) unsigned char sm_raw[];
    const uint32_t sb = s2u(sm_raw);
    const int tid = threadIdx.x, lane = tid & 31, wid = tid >> 5;
    const int itile = 7 - blockIdx.x;          // heaviest first
    const int z = blockIdx.y;
    const int h = z >> 2, b = z & 3;
    const int i0 = itile * 128;
    const int ntile = itile + 1;

    const __nv_bfloat16* Qh = Qh_ + (long)z * 65536;
    const __nv_bfloat16* Ql = Ql_ + (long)z * 65536;
    const __nv_bfloat16* Kh = Kh_ + (long)z * 65536;
    const __nv_bfloat16* Kl = Kl_ + (long)z * 65536;
    const __nv_bfloat16* Vh = Vh_ + (long)z * 65536;
    const __nv_bfloat16* Vl = Vl_ + (long)z * 65536;
    const float* bdz = bd + (long)z * 1048576L;

    // --- load Q tile to stage-0 K slot, pull A fragments to registers ---
    for (int i = tid; i < 1024; i += 256) {
        int row = i >> 3, c8 = i & 7;
        uint32_t off = (uint32_t)(row * 72 + c8 * 8) * 2;
        cpasync16(sb + FL_KH + off, Qh + (long)(i0 + row) * 64 + c8 * 8);
        cpasync16(sb + FL_KL + off, Ql + (long)(i0 + row) * 64 + c8 * 8);
    }
    cp_commit();
    asm volatile("cp.async.wait_group 0;" ::: "memory");
    __syncthreads();

    uint32_t qh[4][4], ql[4][4];
#pragma unroll
    for (int ks = 0; ks < 4; ks++) {
        int row = wid * 16 + (lane & 15);
        int col = ks * 16 + ((lane >> 4) << 3);
        uint32_t ao = (uint32_t)(row * 72 + col) * 2;
        ldsm4(qh[ks], sb + FL_KH + ao);
        ldsm4(ql[ks], sb + FL_KL + ao);
    }
    __syncthreads();   // stage 0 free for K/V

#define FL_ISSUE(T, SS)                                                        \
    {                                                                          \
        uint32_t sd = sb + (SS) * FL_STG;                                      \
        int jj = (T) * 128;                                                    \
        for (int i = tid; i < 1024; i += 256) {                                \
            int row = i >> 3, c8 = i & 7;                                      \
            uint32_t off = (uint32_t)(row * 72 + c8 * 8) * 2;                  \
            cpasync16(sd + FL_KH + off, Kh + (long)(jj + row) * 64 + c8 * 8);  \
            cpasync16(sd + FL_KL + off, Kl + (long)(jj + row) * 64 + c8 * 8);  \
        }                                                                      \
        for (int i = tid; i < 1024; i += 256) {                                \
            int d = i >> 4, c16 = i & 15;                                      \
            uint32_t off = (uint32_t)(d * 136 + c16 * 8) * 2;                  \
            cpasync16(sd + FL_VH + off, Vh + (long)d * 1024 + jj + c16 * 8);   \
            cpasync16(sd + FL_VL + off, Vl + (long)d * 1024 + jj + c16 * 8);   \
        }                                                                      \
        cp_commit();                                                           \
    }

    FL_ISSUE(0, 0)
    if (ntile > 1) FL_ISSUE(1, 1)

    float oacc[8][4];
#pragma unroll
    for (int a = 0; a < 8; a++)
#pragma unroll
        for (int d = 0; d < 4; d++) oacc[a][d] = 0.f;
    float m0 = -1e30f, m1 = -1e30f, l0 = 0.f, l1 = 0.f;

    const int cql = (lane & 3) * 2;
    const int Rg0 = i0 + wid * 16 + (lane >> 2);
    const int Rg1 = Rg0 + 8;

    for (int t = 0; t < ntile; t++) {
        if (t + 1 < ntile)
            asm volatile("cp.async.wait_group 1;" ::: "memory");
        else
            asm volatile("cp.async.wait_group 0;" ::: "memory");
        __syncthreads();

        const uint32_t s0 = sb + (t & 1) * FL_STG;
        const int j0 = t * 128;

        // --- S = Q K^T (3-MMA split) ---
        float sacc[16][4];
#pragma unroll
        for (int nt = 0; nt < 16; nt++)
#pragma unroll
            for (int d = 0; d < 4; d++) sacc[nt][d] = 0.f;

#pragma unroll
        for (int p = 0; p < 8; p++) {
            int brow = p * 16 + ((lane >> 4) << 3) + (lane & 7);
#pragma unroll
            for (int ks = 0; ks < 4; ks++) {
                int bcol = ks * 16 + (((lane >> 3) & 1) << 3);
                uint32_t bo = (uint32_t)(brow * 72 + bcol) * 2;
                uint32_t kf[4], klf[4];
                ldsm4(kf,  s0 + FL_KH + bo);
                ldsm4(klf, s0 + FL_KL + bo);
                mma16816(sacc[2 * p],     qh[ks], &kf[0]);
                mma16816(sacc[2 * p + 1], qh[ks], &kf[2]);
                mma16816(sacc[2 * p],     qh[ks], &klf[0]);
                mma16816(sacc[2 * p + 1], qh[ks], &klf[2]);
                mma16816(sacc[2 * p],     ql[ks], &kf[0]);
                mma16816(sacc[2 * p + 1], ql[ks], &kf[2]);
            }
        }

        // --- fused BD shift-add + scale + causal mask, row maxima ---
        float mx0 = -1e30f, mx1 = -1e30f;
#pragma unroll
        for (int nt = 0; nt < 16; nt++) {
            int Cg = j0 + nt * 8 + cql;
            float v0 = (Cg     <= Rg0) ? (sacc[nt][0] + bdz[(long)Rg0 * 1024 + Cg     + 1023 - Rg0]) * 0.125f : -1e30f;
            float v1 = (Cg + 1 <= Rg0) ? (sacc[nt][1] + bdz[(long)Rg0 * 1024 + Cg + 1 + 1023 - Rg0]) * 0.125f : -1e30f;
            float v2 = (Cg     <= Rg1) ? (sacc[nt][2] + bdz[(long)Rg1 * 1024 + Cg     + 1023 - Rg1]) * 0.125f : -1e30f;
            float v3 = (Cg + 1 <= Rg1) ? (sacc[nt][3] + bdz[(long)Rg1 * 1024 + Cg + 1 + 1023 - Rg1]) * 0.125f : -1e30f;
            sacc[nt][0] = v0; sacc[nt][1] = v1; sacc[nt][2] = v2; sacc[nt][3] = v3;
            mx0 = fmaxf(mx0, fmaxf(v0, v1));
            mx1 = fmaxf(mx1, fmaxf(v2, v3));
        }
        mx0 = fmaxf(mx0, __shfl_xor_sync(0xffffffffu, mx0, 1));
        mx0 = fmaxf(mx0, __shfl_xor_sync(0xffffffffu, mx0, 2));
        mx1 = fmaxf(mx1, __shfl_xor_sync(0xffffffffu, mx1, 1));
        mx1 = fmaxf(mx1, __shfl_xor_sync(0xffffffffu, mx1, 2));

        // --- online rescale ---
        float mn0 = fmaxf(m0, mx0), mn1 = fmaxf(m1, mx1);
        float al0 = __expf(m0 - mn0), al1 = __expf(m1 - mn1);
        m0 = mn0; m1 = mn1;
        l0 *= al0; l1 *= al1;
#pragma unroll
        for (int on = 0; on < 8; on++) {
            oacc[on][0] *= al0; oacc[on][1] *= al0;
            oacc[on][2] *= al1; oacc[on][3] *= al1;
        }
#pragma unroll
        for (int nt = 0; nt < 16; nt++) {
            float p0 = __expf(sacc[nt][0] - mn0);
            float p1 = __expf(sacc[nt][1] - mn0);
            float p2 = __expf(sacc[nt][2] - mn1);
            float p3 = __expf(sacc[nt][3] - mn1);
            l0 += p0 + p1; l1 += p2 + p3;
            sacc[nt][0] = p0; sacc[nt][1] = p1; sacc[nt][2] = p2; sacc[nt][3] = p3;
        }

        // --- PV: P (c-frag -> a-frag identity) times V, 3-MMA split ---
#pragma unroll
        for (int kt = 0; kt < 8; kt++) {
            uint32_t phi[4], plo[4];
            splitpack(sacc[2 * kt][0],     sacc[2 * kt][1],     phi[0], plo[0]);
            splitpack(sacc[2 * kt][2],     sacc[2 * kt][3],     phi[1], plo[1]);
            splitpack(sacc[2 * kt + 1][0], sacc[2 * kt + 1][1], phi[2], plo[2]);
            splitpack(sacc[2 * kt + 1][2], sacc[2 * kt + 1][3], phi[3], plo[3]);
#pragma unroll
            for (int vp = 0; vp < 4; vp++) {
                int vrow = vp * 16 + ((lane >> 4) << 3) + (lane & 7);
                int vcol = kt * 16 + (((lane >> 3) & 1) << 3);
                uint32_t vo = (uint32_t)(vrow * 136 + vcol) * 2;
                uint32_t vhf[4], vlf[4];
                ldsm4(vhf, s0 + FL_VH + vo);
                ldsm4(vlf, s0 + FL_VL + vo);
                mma16816(oacc[2 * vp],     phi, &vhf[0]);
                mma16816(oacc[2 * vp + 1], phi, &vhf[2]);
                mma16816(oacc[2 * vp],     phi, &vlf[0]);
                mma16816(oacc[2 * vp + 1], phi, &vlf[2]);
                mma16816(oacc[2 * vp],     plo, &vhf[0]);
                mma16816(oacc[2 * vp + 1], plo, &vhf[2]);
            }
        }

        __syncthreads();                       // all warps done with stage (t&1)
        if (t + 2 < ntile) FL_ISSUE(t + 2, (t & 1))
    }

    // --- finalize: quad-reduce l, normalize, write split-bf16 operand ---
    l0 += __shfl_xor_sync(0xffffffffu, l0, 1);
    l0 += __shfl_xor_sync(0xffffffffu, l0, 2);
    l1 += __shfl_xor_sync(0xffffffffu, l1, 1);
    l1 += __shfl_xor_sync(0xffffffffu, l1, 2);
    const float r0 = 1.f / l0, r1 = 1.f / l1;

    const long tok0 = (long)(Rg0 * 4 + b) * 1024 + h * 64;
    const long tok1 = (long)(Rg1 * 4 + b) * 1024 + h * 64;
#pragma unroll
    for (int on = 0; on < 8; on++) {
        int d = on * 8 + cql;
        uint32_t hw, lw;
        splitpack(oacc[on][0] * r0, oacc[on][1] * r0, hw, lw);
        *(uint32_t*)(outh + tok0 + d) = hw;
        *(uint32_t*)(outl + tok0 + d) = lw;
        splitpack(oacc[on][2] * r1, oacc[on][3] * r1, hw, lw);
        *(uint32_t*)(outh + tok1 + d) = hw;
        *(uint32_t*)(outl + tok1 + d) = lw;
    }
#undef FL_ISSUE
}

// ---------------------------------------------------------------------------
// Conv as batched HMMA GEMM (unchanged from R14)
// ---------------------------------------------------------------------------
#define APITCH 72
#define BPITCH 456
#define CV_AH 0
#define CV_AL 19296
#define CV_BH 38592
#define CV_BL 96960
#define CV_SMEM 155328

__global__ __launch_bounds__(256)
void conv_mma_k(const float* __restrict__ heads,
                const __nv_bfloat16* __restrict__ cwh, const __nv_bfloat16* __restrict__ cwl,
                const float* __restrict__ cbq, const float* __restrict__ cbk,
                const float* __restrict__ cbv,
                const float* __restrict__ rwb, const float* __restrict__ rrb,
                __nv_bfloat16* __restrict__ qwh, __nv_bfloat16* __restrict__ qwl,
                __nv_bfloat16* __restrict__ qrh, __nv_bfloat16* __restrict__ qrl,
                __nv_bfloat16* __restrict__ khh, __nv_bfloat16* __restrict__ khl,
                __nv_bfloat16* __restrict__ vhh, __nv_bfloat16* __restrict__ vhl)
{
    extern __shared__ __align__(16) unsigned char sm_raw[];
    const uint32_t sb = s2u(sm_raw);
    const int tid = threadIdx.x, lane = tid & 31, wid = tid >> 5;
    const int l0 = blockIdx.x * 128;
    const int z  = blockIdx.y;
    const int s  = blockIdx.z;
    const int h  = z >> 2, b = z & 3;
    const int wm = wid & 3, wn = wid >> 2;

    const __nv_bfloat16* wph = cwh + (long)s * (64 * 448);
    const __nv_bfloat16* wpl = cwl + (long)s * (64 * 448);
    for (int i = tid; i < 64 * 56; i += 256) {
        int o = i / 56, c = i % 56;
        uint32_t so = (uint32_t)(o * BPITCH + c * 8) * 2;
        cpasync16(sb + CV_BH + so, wph + o * 448 + c * 8);
        cpasync16(sb + CV_BL + so, wpl + o * 448 + c * 8);
    }
    cp_commit();

    const float* hsrc = heads + (long)b * 3072 + s * 1024 + h * 64;
    for (int i = tid; i < 134 * 16; i += 256) {
        int r = i / 16, c4 = i % 16;
        int lg = l0 - 3 + r;
        float4 v = make_float4(0.f, 0.f, 0.f, 0.f);
        if (lg >= 0 && lg < 1024)
            v = *(const float4*)(hsrc + (long)lg * 4 * 3072 + c4 * 4);
        uint32_t h0, lw0, h1, lw1;
        splitpack(v.x, v.y, h0, lw0);
        splitpack(v.z, v.w, h1, lw1);
        uint32_t off = (uint32_t)(r * APITCH + c4 * 4) * 2;
        *(uint2*)(sm_raw + CV_AH + off) = make_uint2(h0, h1);
        *(uint2*)(sm_raw + CV_AL + off) = make_uint2(lw0, lw1);
    }
    asm volatile("cp.async.wait_group 0;" ::: "memory");
    __syncthreads();

    float acc[2][4][4];
#pragma unroll
    for (int a = 0; a < 2; a++)
#pragma unroll
        for (int c = 0; c < 4; c++)
#pragma unroll
            for (int d = 0; d < 4; d++) acc[a][c][d] = 0.f;

    for (int t = 0; t < 7; t++) {
#pragma unroll
        for (int dk = 0; dk < 4; dk++) {
            uint32_t ah[2][4], al[2][4], bh[2][4], bl[2][4];
#pragma unroll
            for (int mt = 0; mt < 2; mt++) {
                int row = wm * 32 + mt * 16 + (lane & 15) + t;
                int col = dk * 16 + ((lane >> 4) << 3);
                uint32_t ao = (uint32_t)(row * APITCH + col) * 2;
                ldsm4(ah[mt], sb + CV_AH + ao);
                ldsm4(al[mt], sb + CV_AL + ao);
            }
#pragma unroll
            for (int p = 0; p < 2; p++) {
                int row = wn * 32 + p * 16 + ((lane >> 4) << 3) + (lane & 7);
                int col = t * 64 + dk * 16 + (((lane >> 3) & 1) << 3);
                uint32_t bo = (uint32_t)(row * BPITCH + col) * 2;
                ldsm4(bh[p], sb + CV_BH + bo);
                ldsm4(bl[p], sb + CV_BL + bo);
            }
#pragma unroll
            for (int mt = 0; mt < 2; mt++)
#pragma unroll
                for (int nt = 0; nt < 4; nt++)
                    mma16816(acc[mt][nt], ah[mt], &bh[nt >> 1][(nt & 1) * 2]);
#pragma unroll
            for (int mt = 0; mt < 2; mt++)
#pragma unroll
                for (int nt = 0; nt < 4; nt++)
                    mma16816(acc[mt][nt], ah[mt], &bl[nt >> 1][(nt & 1) * 2]);
#pragma unroll
            for (int mt = 0; mt < 2; mt++)
#pragma unroll
                for (int nt = 0; nt < 4; nt++)
                    mma16816(acc[mt][nt], al[mt], &bh[nt >> 1][(nt & 1) * 2]);
        }
    }

    if (s == 2) {
        __syncthreads();
        float* stg = (float*)sm_raw;
#pragma unroll
        for (int mt = 0; mt < 2; mt++) {
            int rl = wm * 32 + mt * 16 + (lane >> 2);
#pragma unroll
            for (int nt = 0; nt < 4; nt++) {
                int cd = wn * 32 + nt * 8 + (lane & 3) * 2;
                float b0 = cbv[cd], b1 = cbv[cd + 1];
                stg[rl * 68 + cd]           = acc[mt][nt][0] + b0;
                stg[rl * 68 + cd + 1]       = acc[mt][nt][1] + b1;
                stg[(rl + 8) * 68 + cd]     = acc[mt][nt][2] + b0;
                stg[(rl + 8) * 68 + cd + 1] = acc[mt][nt][3] + b1;
            }
        }
        __syncthreads();
        const int d  = tid >> 2;
        const int lb = (tid & 3) * 32;
        long ob = ((long)z * 64 + d) * 1024 + l0 + lb;
#pragma unroll
        for (int j = 0; j < 32; j += 2) {
            float v0 = stg[(lb + j) * 68 + d];
            float v1 = stg[(lb + j + 1) * 68 + d];
            uint32_t hw, lw;
            splitpack(v0, v1, hw, lw);
            *(uint32_t*)(vhh + ob + j) = hw;
            *(uint32_t*)(vhl + ob + j) = lw;
        }
        return;
    }

#pragma unroll
    for (int mt = 0; mt < 2; mt++) {
        int rl = wm * 32 + mt * 16 + (lane >> 2);
#pragma unroll
        for (int nt = 0; nt < 4; nt++) {
            int cd = wn * 32 + nt * 8 + (lane & 3) * 2;
#pragma unroll
            for (int rr = 0; rr < 2; rr++) {
                int R = rl + rr * 8;
                long ob = ((long)z * 1024 + l0 + R) * 64 + cd;
                float v0 = acc[mt][nt][rr * 2 + 0];
                float v1 = acc[mt][nt][rr * 2 + 1];
                uint32_t hw, lw;
                if (s == 0) {
                    float c0 = cbq[cd], c1 = cbq[cd + 1];
                    splitpack(v0 + c0 + rwb[h * 64 + cd], v1 + c1 + rwb[h * 64 + cd + 1], hw, lw);
                    *(uint32_t*)(qwh + ob) = hw;
                    *(uint32_t*)(qwl + ob) = lw;
                    splitpack(v0 + c0 + rrb[h * 64 + cd], v1 + c1 + rrb[h * 64 + cd + 1], hw, lw);
                    *(uint32_t*)(qrh + ob) = hw;
                    *(uint32_t*)(qrl + ob) = lw;
                } else {
                    splitpack(v0 + cbk[cd], v1 + cbk[cd + 1], hw, lw);
                    *(uint32_t*)(khh + ob) = hw;
                    *(uint32_t*)(khl + ob) = lw;
                }
            }
        }
    }
}

// ---------------------------------------------------------------------------
// SIMT SGEMM (rproj only)
// ---------------------------------------------------------------------------
template<int BM,int BN,int BK,int TM,int TN>
__global__ __launch_bounds__((BM/TM)*(BN/TN))
void gemm_k(const float* __restrict__ A, const float* __restrict__ B,
            float* __restrict__ C, int K, int lda, int ldb, int ldc)
{
    constexpr int TX = BN / TN;
    constexpr int TY = BM / TM;
    constexpr int NT = TX * TY;
    constexpr int NA = BM * BK / 4;
    constexpr int NB = BN * BK / 4;
    constexpr int LA = (NA + NT - 1) / NT;
    constexpr int LB = (NB + NT - 1) / NT;

    const int tid = threadIdx.x;
    const int m0  = blockIdx.y * BM;
    const int n0  = blockIdx.x * BN;

    __shared__ float As[2][BK][BM + 4];
    __shared__ float Bs[2][BK][BN + 4];

    const int tx = tid % TX;
    const int ty = tid / TX;

    float acc[TM][TN];
#pragma unroll
    for (int i = 0; i < TM; i++)
#pragma unroll
        for (int j = 0; j < TN; j++) acc[i][j] = 0.f;

    float4 ra[LA], rb[LB];

#define LOAD_AB(K0)                                                            \
    _Pragma("unroll")                                                          \
    for (int u = 0; u < LA; u++) {                                             \
        int i = tid + u * NT;                                                  \
        int r = i / (BK/4), q = i % (BK/4);                                    \
        ra[u] = *(const float4*)(A + (long)(m0 + r) * lda + (K0) + q*4);       \
    }                                                                          \
    _Pragma("unroll")                                                          \
    for (int u = 0; u < LB; u++) {                                             \
        int i = tid + u * NT;                                                  \
        int r = i / (BK/4), q = i % (BK/4);                                    \
        rb[u] = *(const float4*)(B + (long)(n0 + r) * ldb + (K0) + q*4);       \
    }
#define STORE_AB(BUF)                                                          \
    _Pragma("unroll")                                                          \
    for (int u = 0; u < LA; u++) {                                             \
        int i = tid + u * NT;                                                  \
        int r = i / (BK/4), q = i % (BK/4);                                    \
        As[BUF][q*4+0][r] = ra[u].x; As[BUF][q*4+1][r] = ra[u].y;              \
        As[BUF][q*4+2][r] = ra[u].z; As[BUF][q*4+3][r] = ra[u].w;              \
    }                                                                          \
    _Pragma("unroll")                                                          \
    for (int u = 0; u < LB; u++) {                                             \
        int i = tid + u * NT;                                                  \
        int r = i / (BK/4), q = i % (BK/4);                                    \
        Bs[BUF][q*4+0][r] = rb[u].x; Bs[BUF][q*4+1][r] = rb[u].y;              \
        Bs[BUF][q*4+2][r] = rb[u].z; Bs[BUF][q*4+3][r] = rb[u].w;              \
    }

    LOAD_AB(0)
    STORE_AB(0)
    __syncthreads();

    const int ktiles = K / BK;
    for (int t = 0; t < ktiles; t++) {
        const int cur = t & 1;
        if (t + 1 < ktiles) { LOAD_AB((t + 1) * BK) }
#pragma unroll
        for (int kk = 0; kk < BK; kk++) {
            float a[TM], bb[TN];
#pragma unroll
            for (int u = 0; u < TM / 4; u++)
                *(float4*)&a[u * 4] = *(const float4*)&As[cur][kk][ty * TM + u * 4];
#pragma unroll
            for (int u = 0; u < TN / 4; u++)
                *(float4*)&bb[u * 4] = *(const float4*)&Bs[cur][kk][tx * TN + u * 4];
#pragma unroll
            for (int i = 0; i < TM; i++)
#pragma unroll
                for (int j = 0; j < TN; j++)
                    acc[i][j] += a[i] * bb[j];
        }
        if (t + 1 < ktiles) {
            STORE_AB(cur ^ 1)
            __syncthreads();
        }
    }

#pragma unroll
    for (int i = 0; i < TM; i++) {
        long row = m0 + ty * TM + i;
#pragma unroll
        for (int u = 0; u < TN / 4; u++) {
            float4 v = make_float4(acc[i][u*4+0], acc[i][u*4+1],
                                   acc[i][u*4+2], acc[i][u*4+3]);
            *(float4*)(C + row * ldc + n0 + tx * TN + u * 4) = v;
        }
    }
#undef LOAD_AB
#undef STORE_AB
}

// ---------------------------------------------------------------------------
// Fused residual + LayerNorm
// ---------------------------------------------------------------------------
__global__ __launch_bounds__(256)
void ln_k(const float* __restrict__ w, const float* __restrict__ attn,
          const float* __restrict__ gamma, const float* __restrict__ beta,
          float* __restrict__ out)
{
    const long t = blockIdx.x;
    __shared__ float xs[1024];
    __shared__ float red[8];
    const int tid = threadIdx.x, lane = tid & 31, wid = tid >> 5;

    float s = 0.f;
    for (int j = tid; j < 1024; j += 256) {
        float v = w[t * 1024 + j] + attn[t * 1024 + j];
        xs[j] = v;
        s += v;
    }
#pragma unroll
    for (int o = 16; o > 0; o >>= 1) s += __shfl_xor_sync(0xffffffffu, s, o);
    if (lane == 0) red[wid] = s;
    __syncthreads();
    if (tid == 0) {
        float tot = 0.f;
#pragma unroll
        for (int k = 0; k < 8; k++) tot += red[k];
        red[0] = tot * (1.f / 1024.f);
    }
    __syncthreads();
    const float mu = red[0];
    __syncthreads();

    float vs = 0.f;
    for (int j = tid; j < 1024; j += 256) {
        float d = xs[j] - mu;
        vs += d * d;
    }
#pragma unroll
    for (int o = 16; o > 0; o >>= 1) vs += __shfl_xor_sync(0xffffffffu, vs, o);
    if (lane == 0) red[wid] = vs;
    __syncthreads();
    if (tid == 0) {
        float tot = 0.f;
#pragma unroll
        for (int k = 0; k < 8; k++) tot += red[k];
        red[0] = rsqrtf(tot * (1.f / 1024.f) + 1e-5f);
    }
    __syncthreads();
    const float rstd = red[0];
    for (int j = tid; j < 1024; j += 256)
        out[t * 1024 + j] = (xs[j] - mu) * rstd * gamma[j] + beta[j];
}

// ---------------------------------------------------------------------------
// Orchestration
// ---------------------------------------------------------------------------
extern "C" void kernel_launch(void* const* d_in, const int* in_sizes, int n_in,
                              void* d_out, int out_size)
{
    (void)in_sizes; (void)n_in; (void)out_size;
    const float* w     = (const float*)d_in[0];
    const float* r     = (const float*)d_in[1];
    const float* rwb   = (const float*)d_in[2];
    const float* rrb   = (const float*)d_in[3];
    const float* Wqkv  = (const float*)d_in[4];
    const float* Wr    = (const float*)d_in[5];
    const float* Wo    = (const float*)d_in[6];
    const float* cwq   = (const float*)d_in[7];
    const float* cbq   = (const float*)d_in[8];
    const float* cwk   = (const float*)d_in[9];
    const float* cbk   = (const float*)d_in[10];
    const float* cwv   = (const float*)d_in[11];
    const float* cbv   = (const float*)d_in[12];
    const float* gamma = (const float*)d_in[13];
    const float* beta  = (const float*)d_in[14];
    float* out = (float*)d_out;

    float *heads, *rproj, *bd, *attn;
    __nv_bfloat16 *ahi, *alo, *bhi, *blo, *whi, *wlo, *cwh, *cwl;
    __nv_bfloat16 *qwh, *qwl, *qrh, *qrl, *khh, *khl, *vhh, *vhl, *rph, *rpl;
    cudaGetSymbolAddress((void**)&heads,  g_heads);
    cudaGetSymbolAddress((void**)&rproj,  g_rproj);
    cudaGetSymbolAddress((void**)&bd,     g_bd);
    cudaGetSymbolAddress((void**)&attn,   g_attn);
    cudaGetSymbolAddress((void**)&ahi,    g_ahi);
    cudaGetSymbolAddress((void**)&alo,    g_alo);
    cudaGetSymbolAddress((void**)&bhi,    g_bhi);
    cudaGetSymbolAddress((void**)&blo,    g_blo);
    cudaGetSymbolAddress((void**)&whi,    g_whi);
    cudaGetSymbolAddress((void**)&wlo,    g_wlo);
    cudaGetSymbolAddress((void**)&cwh,    g_cwh);
    cudaGetSymbolAddress((void**)&cwl,    g_cwl);
    cudaGetSymbolAddress((void**)&qwh,    g_qwh);
    cudaGetSymbolAddress((void**)&qwl,    g_qwl);
    cudaGetSymbolAddress((void**)&qrh,    g_qrh);
    cudaGetSymbolAddress((void**)&qrl,    g_qrl);
    cudaGetSymbolAddress((void**)&khh,    g_khh);
    cudaGetSymbolAddress((void**)&khl,    g_khl);
    cudaGetSymbolAddress((void**)&vhh,    g_vhh);
    cudaGetSymbolAddress((void**)&vhl,    g_vhl);
    cudaGetSymbolAddress((void**)&rph,    g_rph);
    cudaGetSymbolAddress((void**)&rpl,    g_rpl);

    const int SM128 = 2 * (2 * 128 * 40 * 2 + 2 * 128 * 40 * 2);
    cudaFuncSetAttribute(mma_batch_k<128,0>, cudaFuncAttributeMaxDynamicSharedMemorySize, SM128);
    cudaFuncSetAttribute(mma_batch_k<128,2>, cudaFuncAttributeMaxDynamicSharedMemorySize, SM128);
    cudaFuncSetAttribute(conv_mma_k, cudaFuncAttributeMaxDynamicSharedMemorySize, CV_SMEM);
    cudaFuncSetAttribute(flash_k,    cudaFuncAttributeMaxDynamicSharedMemorySize, FL_SMEM);

    // 1. packs
    pack2_k<<<4096, 256>>>(w,    ahi, alo, 4096 * 256);
    pack2_k<<<3072, 256>>>(Wqkv, bhi, blo, 3072 * 256);
    pack2_k<<<1024, 256>>>(Wo,   whi, wlo, 1024 * 256);
    prep_cw_k<<<(3 * 64 * 448 + 255) / 256, 256>>>(cwq, cwk, cwv, cwh, cwl);

    // 2. heads = w @ Wqkv^T (HMMA)
    mma_batch_k<128,0><<<dim3(24, 32, 1), 256, SM128>>>(
        ahi, alo, bhi, blo, heads, 1024, 1024, 3072, 1024, 0, 0, 0, 0);

    // 3. rproj = r @ Wr^T + pack
    gemm_k<128,128,8,8,8><<<dim3(8, 8, 1), 256>>>(r, Wr, rproj, 1024, 1024, 1024, 1024);
    pack2_k<<<1024, 256>>>(rproj, rph, rpl, 1024 * 256);

    // 4. conv as HMMA GEMM (emits all attention operands, split-bf16)
    conv_mma_k<<<dim3(8, 64, 3), 256, CV_SMEM>>>(
        heads, cwh, cwl, cbq, cbk, cbv, rwb, rrb,
        qwh, qwl, qrh, qrl, khh, khl, vhh, vhl);

    // 5. BD raw (HMMA, band skip)
    mma_batch_k<128,2><<<dim3(8, 8, 64), 256, SM128>>>(
        qrh, qrl, rph, rpl, bd, 64, 1024, 1024, 64, 65536L, 64L, 1, 1048576L);

    // 6. fused flash attention -> Wo operand (split-bf16, reuses ahi/alo)
    flash_k<<<dim3(8, 64), 256, FL_SMEM>>>(
        qwh, qwl, khh, khl, vhh, vhl, bd, ahi, alo);

    // 7. attn = vec @ Wo^T (HMMA)
    mma_batch_k<128,0><<<dim3(8, 32, 1), 256, SM128>>>(
        ahi, alo, whi, wlo, attn, 1024, 1024, 1024, 1024, 0, 0, 0, 0);

    // 8. out = LayerNorm(w + attn)
    ln_k<<<4096, 256>>>(w, attn, gamma, beta, out);
}